// round 6
// baseline (speedup 1.0000x reference)
#include <cuda_runtime.h>
#include <cuda_bf16.h>
#include <cstdint>

#define NN 50000
#define NE 1600000
#define EP 1650000     // NE + NN self loops
#define FW 128         // H*C feature width
#define GS 136         // smem stride (floats): banks = 8*tig + g, conflict-free

// ---------------- scratch (device globals; no allocation allowed) ------------
__device__ float g_xl[(size_t)NN * FW];
__device__ float g_xr[(size_t)NN * FW];
__device__ float g_h [(size_t)NN * FW];
__device__ float g_agg[(size_t)NN * FW];
__device__ float g_denom[NN * 4];          // sum of exp(logit); inverted in-place
__device__ float g_ewsum;
__device__ float g_whi[4][128 * 128];      // tf32-hi of the 4 weight matrices
__device__ float g_wlo[4][128 * 128];      // tf32-lo remainder

// ---------------- edge-weight mean -------------------------------------------
__global__ void k_zero_scalar() { g_ewsum = 0.f; }

__global__ void k_ew_reduce(const float* __restrict__ ew) {
    float s = 0.f;
    int stride = gridDim.x * blockDim.x;
    for (int i = blockIdx.x * blockDim.x + threadIdx.x; i < NE; i += stride)
        s += ew[i];
    #pragma unroll
    for (int o = 16; o; o >>= 1) s += __shfl_xor_sync(0xffffffffu, s, o);
    __shared__ float sm[8];
    int w = threadIdx.x >> 5, l = threadIdx.x & 31;
    if (l == 0) sm[w] = s;
    __syncthreads();
    if (threadIdx.x < 8) {
        s = sm[threadIdx.x];
        #pragma unroll
        for (int o = 4; o; o >>= 1) s += __shfl_xor_sync(0x000000ffu, s, o, 8);
        if (threadIdx.x == 0) atomicAdd(&g_ewsum, s);
    }
}

// ---------------- tf32 helpers ------------------------------------------------
__device__ __forceinline__ void tf32split(float x, uint32_t& hi, uint32_t& lo) {
    uint32_t h;
    asm("cvt.rna.tf32.f32 %0, %1;" : "=r"(h) : "f"(x));
    float r = x - __uint_as_float(h);
    uint32_t l;
    asm("cvt.rna.tf32.f32 %0, %1;" : "=r"(l) : "f"(r));
    hi = h; lo = l;
}

// split all four 128x128 weight matrices once
__global__ void k_wsplit(const float* __restrict__ W0, const float* __restrict__ W1,
                         const float* __restrict__ W2, const float* __restrict__ W3) {
    int i = blockIdx.x * blockDim.x + threadIdx.x;   // 0..65535
    if (i >= 4 * 16384) return;
    int m = i >> 14, j = i & 16383;
    const float* W = (m == 0) ? W0 : (m == 1) ? W1 : (m == 2) ? W2 : W3;
    uint32_t h, l;
    tf32split(W[j], h, l);
    g_whi[m][j] = __uint_as_float(h);
    g_wlo[m][j] = __uint_as_float(l);
}

#define MMA_TF32(ACC, A0, A1, A2, A3, B0, B1)                                   \
    asm volatile("mma.sync.aligned.m16n8k8.row.col.f32.tf32.tf32.f32 "          \
                 "{%0,%1,%2,%3},{%4,%5,%6,%7},{%8,%9},{%0,%1,%2,%3};"           \
                 : "+f"(ACC[0]), "+f"(ACC[1]), "+f"(ACC[2]), "+f"(ACC[3])       \
                 : "r"(A0), "r"(A1), "r"(A2), "r"(A3), "r"(B0), "r"(B1))

// ---------------- tensor-core GEMM: C[M,128] = A[M,128] @ W[128,128] ---------
// 3xTF32 (ah*bh + ah*bl + al*bh). Block = 8 warps, 2 blocks/SM (69.6KB smem):
// warp = 16 rows x 64 cols (warp&1 selects column half). W-hi staged in smem
// (conflict-free GS=136), W-lo fragments read from pre-split global (L1-hot).
__global__ void __launch_bounds__(256, 2) k_gemm_tc(
        const float* __restrict__ Aext, int asel, int widx, int csel) {
    const float* __restrict__ A = asel ? g_h : Aext;
    float* __restrict__ C = csel ? g_xr : g_xl;

    extern __shared__ float sw[];          // [128][GS] tf32-hi
    {
        const float4* __restrict__ src = (const float4*)&g_whi[widx][0];
        int tid = threadIdx.x;
        #pragma unroll
        for (int i = tid; i < 4096; i += 256) {
            int k = i >> 5, c = i & 31;
            *(float4*)&sw[k * GS + c * 4] = src[i];
        }
    }
    __syncthreads();

    int tid = threadIdx.x;
    int warp = tid >> 5, lane = tid & 31;
    int g = lane >> 2, tig = lane & 3;
    int wr = warp >> 1, n0 = (warp & 1) * 64;
    int r0 = blockIdx.x * 64 + wr * 16;
    if (r0 >= NN) return;                  // NN % 16 == 0: no partial warps

    const float* __restrict__ arow0 = A + (size_t)(r0 + g) * 128;
    const float* __restrict__ arow1 = A + (size_t)(r0 + g + 8) * 128;
    const float* __restrict__ wl = &g_wlo[widx][0];

    float acc[8][4];
    #pragma unroll
    for (int n = 0; n < 8; n++)
        #pragma unroll
        for (int j = 0; j < 4; j++) acc[n][j] = 0.f;

    #pragma unroll 4
    for (int ks = 0; ks < 16; ks++) {
        int k0 = ks * 8;
        uint32_t ah[4], al[4];
        tf32split(arow0[k0 + tig],     ah[0], al[0]);
        tf32split(arow1[k0 + tig],     ah[1], al[1]);
        tf32split(arow0[k0 + tig + 4], ah[2], al[2]);
        tf32split(arow1[k0 + tig + 4], ah[3], al[3]);

        const float* sh0 = &sw[(k0 + tig) * GS + n0 + g];
        const float* sh1 = &sw[(k0 + tig + 4) * GS + n0 + g];
        const float* gl0 = &wl[(k0 + tig) * 128 + n0 + g];
        const float* gl1 = &wl[(k0 + tig + 4) * 128 + n0 + g];

        #pragma unroll
        for (int n = 0; n < 8; n++) {
            uint32_t bh0 = __float_as_uint(sh0[n * 8]);
            uint32_t bh1 = __float_as_uint(sh1[n * 8]);
            uint32_t bl0 = __float_as_uint(gl0[n * 8]);
            uint32_t bl1 = __float_as_uint(gl1[n * 8]);
            MMA_TF32(acc[n], ah[0], ah[1], ah[2], ah[3], bh0, bh1);
            MMA_TF32(acc[n], ah[0], ah[1], ah[2], ah[3], bl0, bl1);
            MMA_TF32(acc[n], al[0], al[1], al[2], al[3], bh0, bh1);
        }
    }

    float* c0 = C + (size_t)(r0 + g) * 128 + n0 + 2 * tig;
    float* c1 = C + (size_t)(r0 + g + 8) * 128 + n0 + 2 * tig;
    #pragma unroll
    for (int n = 0; n < 8; n++) {
        *(float2*)&c0[n * 8] = make_float2(acc[n][0], acc[n][1]);
        *(float2*)&c1[n * 8] = make_float2(acc[n][2], acc[n][3]);
    }
}

// ---------------- per-layer init (zero agg + denom) ---------------------------
__global__ void k_init() {
    int i = blockIdx.x * blockDim.x + threadIdx.x;
    if (i < NN * FW / 4) ((float4*)g_agg)[i] = make_float4(0.f, 0.f, 0.f, 0.f);
    if (i < NN * 4) g_denom[i] = 0.f;
}

// ---------------- SINGLE fused edge pass (warp per edge) ---------------------
// logit -> p=exp(logit) -> denom += p ; agg += p * xl[src]  (unnormalized).
// Normalization happens in the per-node epilogue (denom const per dst,head).
__global__ void k_edge(const int* __restrict__ esrc, const int* __restrict__ edst,
                       const float* __restrict__ ew,
                       const float* __restrict__ We, const float* __restrict__ att) {
    int e = (blockIdx.x * blockDim.x + threadIdx.x) >> 5;
    if (e >= EP) return;
    int lane = threadIdx.x & 31;
    int s, d; float w;
    if (e < NE) { s = esrc[e]; d = edst[e]; w = ew[e]; }
    else        { s = d = e - NE; w = g_ewsum * (1.0f / NE); }

    float4 a  = *(const float4*)&g_xl[(size_t)s * 128 + lane * 4];
    float4 b  = *(const float4*)&g_xr[(size_t)d * 128 + lane * 4];
    float4 we = *(const float4*)&We[lane * 4];
    float4 at = *(const float4*)&att[lane * 4];

    float z0 = a.x + b.x + w * we.x; z0 = z0 > 0.f ? z0 : 0.2f * z0;
    float z1 = a.y + b.y + w * we.y; z1 = z1 > 0.f ? z1 : 0.2f * z1;
    float z2 = a.z + b.z + w * we.z; z2 = z2 > 0.f ? z2 : 0.2f * z2;
    float z3 = a.w + b.w + w * we.w; z3 = z3 > 0.f ? z3 : 0.2f * z3;

    float p = z0 * at.x + z1 * at.y + z2 * at.z + z3 * at.w;
    p += __shfl_xor_sync(0xffffffffu, p, 1);
    p += __shfl_xor_sync(0xffffffffu, p, 2);
    p += __shfl_xor_sync(0xffffffffu, p, 4);

    float pe = __expf(p);
    if ((lane & 7) == 0)
        atomicAdd(&g_denom[d * 4 + (lane >> 3)], pe);

    float* dst = &g_agg[(size_t)d * 128 + lane * 4];
    asm volatile("red.global.add.v4.f32 [%0], {%1,%2,%3,%4};"
                 :: "l"(dst), "f"(a.x * pe), "f"(a.y * pe),
                    "f"(a.z * pe), "f"(a.w * pe) : "memory");
}

// ---------------- denom -> reciprocal ----------------------------------------
__global__ void k_inv() {
    int i = blockIdx.x * blockDim.x + threadIdx.x;
    if (i < NN * 4) g_denom[i] = 1.0f / (g_denom[i] + 1e-16f);
}

// ---------------- layer-1 epilogue: normalize + bias + ELU -> g_h ------------
__global__ void k_elu(const float* __restrict__ b1) {
    int idx = blockIdx.x * blockDim.x + threadIdx.x;
    if (idx >= NN * FW) return;
    int n = idx >> 7, h = (idx >> 5) & 3;
    float v = g_agg[idx] * g_denom[n * 4 + h] + b1[idx & 127];
    g_h[idx] = v > 0.f ? v : (__expf(v) - 1.f);
}

// ---------------- layer-2 epilogue: normalize + head-mean + bias -> out ------
__global__ void k_final(const float* __restrict__ b2, float* __restrict__ out) {
    int idx = blockIdx.x * blockDim.x + threadIdx.x;
    if (idx >= NN * 32) return;
    int n = idx >> 5, c = idx & 31;
    size_t base = (size_t)n * 128 + c;
    const float* inv = &g_denom[n * 4];
    float v = 0.25f * (g_agg[base]      * inv[0] + g_agg[base + 32] * inv[1] +
                       g_agg[base + 64] * inv[2] + g_agg[base + 96] * inv[3]);
    out[idx] = v + b2[c];
}

// ---------------- launch ------------------------------------------------------
extern "C" void kernel_launch(void* const* d_in, const int* in_sizes, int n_in,
                              void* d_out, int out_size) {
    const float* x    = (const float*)d_in[0];
    const int*   ei   = (const int*)  d_in[1];
    const float* ew   = (const float*)d_in[2];
    const float* Wl1  = (const float*)d_in[3];
    const float* Wr1  = (const float*)d_in[4];
    const float* We1  = (const float*)d_in[5];
    const float* att1 = (const float*)d_in[6];
    const float* b1   = (const float*)d_in[7];
    const float* Wl2  = (const float*)d_in[8];
    const float* Wr2  = (const float*)d_in[9];
    const float* We2  = (const float*)d_in[10];
    const float* att2 = (const float*)d_in[11];
    const float* b2   = (const float*)d_in[12];
    float* out = (float*)d_out;

    const int* esrc = ei;
    const int* edst = ei + NE;

    const int SMEM_W = 128 * GS * 4;                    // 69,632 B
    cudaFuncSetAttribute(k_gemm_tc,
                         cudaFuncAttributeMaxDynamicSharedMemorySize, SMEM_W);

    const int TC_BLK   = (NN + 63) / 64;                // 782
    const int INIT_BLK = (NN * FW / 4 + 255) / 256;     // 6250
    const int EW_BLK   = (NN * FW + 255) / 256;         // 25000
    const int EDGE_BLK = EP / 8;                        // 206250 (warp/edge)
    const int INV_BLK  = (NN * 4 + 255) / 256;          // 782
    const int FIN_BLK  = (NN * 32 + 255) / 256;         // 6250

    k_zero_scalar<<<1, 1>>>();
    k_ew_reduce<<<448, 256>>>(ew);
    k_wsplit<<<256, 256>>>(Wl1, Wr1, Wl2, Wr2);

    // ---- layer 1 ----
    k_gemm_tc<<<TC_BLK, 256, SMEM_W>>>(x, 0, 0, 0);   // Wl1 -> xl
    k_gemm_tc<<<TC_BLK, 256, SMEM_W>>>(x, 0, 1, 1);   // Wr1 -> xr
    k_init<<<INIT_BLK, 256>>>();
    k_edge<<<EDGE_BLK, 256>>>(esrc, edst, ew, We1, att1);
    k_inv<<<INV_BLK, 256>>>();
    k_elu<<<EW_BLK, 256>>>(b1);

    // ---- layer 2 ----
    k_gemm_tc<<<TC_BLK, 256, SMEM_W>>>(x, 1, 2, 0);   // Wl2 -> xl
    k_gemm_tc<<<TC_BLK, 256, SMEM_W>>>(x, 1, 3, 1);   // Wr2 -> xr
    k_init<<<INIT_BLK, 256>>>();
    k_edge<<<EDGE_BLK, 256>>>(esrc, edst, ew, We2, att2);
    k_inv<<<INV_BLK, 256>>>();
    k_final<<<FIN_BLK, 256>>>(b2, out);
}

// round 7
// speedup vs baseline: 1.1148x; 1.1148x over previous
#include <cuda_runtime.h>
#include <cuda_bf16.h>
#include <cstdint>

#define NN 50000
#define NE 1600000
#define EP 1650000     // NE + NN self loops
#define FW 128         // H*C feature width
#define GS 136         // smem stride (floats): banks = 8*tig + g, conflict-free

// ---------------- scratch (device globals; no allocation allowed) ------------
__device__ float g_xl[(size_t)NN * FW];
__device__ float g_xr[(size_t)NN * FW];
__device__ float g_h [(size_t)NN * FW];
__device__ float g_agg[(size_t)NN * FW];
__device__ float g_denom[NN * 4];          // sum of exp(logit); inverted in-place
__device__ float g_ewsum;
__device__ float g_whi[4][128 * 128];      // tf32-hi of the 4 weight matrices
__device__ float g_wlo[4][128 * 128];      // tf32-lo remainder

// ---------------- edge-weight mean -------------------------------------------
__global__ void k_zero_scalar() { g_ewsum = 0.f; }

__global__ void k_ew_reduce(const float* __restrict__ ew) {
    float s = 0.f;
    int stride = gridDim.x * blockDim.x;
    for (int i = blockIdx.x * blockDim.x + threadIdx.x; i < NE; i += stride)
        s += ew[i];
    #pragma unroll
    for (int o = 16; o; o >>= 1) s += __shfl_xor_sync(0xffffffffu, s, o);
    __shared__ float sm[8];
    int w = threadIdx.x >> 5, l = threadIdx.x & 31;
    if (l == 0) sm[w] = s;
    __syncthreads();
    if (threadIdx.x < 8) {
        s = sm[threadIdx.x];
        #pragma unroll
        for (int o = 4; o; o >>= 1) s += __shfl_xor_sync(0x000000ffu, s, o, 8);
        if (threadIdx.x == 0) atomicAdd(&g_ewsum, s);
    }
}

// ---------------- tf32 helpers ------------------------------------------------
__device__ __forceinline__ void tf32split(float x, uint32_t& hi, uint32_t& lo) {
    uint32_t h;
    asm("cvt.rna.tf32.f32 %0, %1;" : "=r"(h) : "f"(x));
    float r = x - __uint_as_float(h);
    uint32_t l;
    asm("cvt.rna.tf32.f32 %0, %1;" : "=r"(l) : "f"(r));
    hi = h; lo = l;
}

// split all four 128x128 weight matrices once
__global__ void k_wsplit(const float* __restrict__ W0, const float* __restrict__ W1,
                         const float* __restrict__ W2, const float* __restrict__ W3) {
    int i = blockIdx.x * blockDim.x + threadIdx.x;   // 0..65535
    if (i >= 4 * 16384) return;
    int m = i >> 14, j = i & 16383;
    const float* W = (m == 0) ? W0 : (m == 1) ? W1 : (m == 2) ? W2 : W3;
    uint32_t h, l;
    tf32split(W[j], h, l);
    g_whi[m][j] = __uint_as_float(h);
    g_wlo[m][j] = __uint_as_float(l);
}

#define MMA_TF32(ACC, A0, A1, A2, A3, B0, B1)                                   \
    asm volatile("mma.sync.aligned.m16n8k8.row.col.f32.tf32.tf32.f32 "          \
                 "{%0,%1,%2,%3},{%4,%5,%6,%7},{%8,%9},{%0,%1,%2,%3};"           \
                 : "+f"(ACC[0]), "+f"(ACC[1]), "+f"(ACC[2]), "+f"(ACC[3])       \
                 : "r"(A0), "r"(A1), "r"(A2), "r"(A3), "r"(B0), "r"(B1))

// ---------------- tensor-core GEMM: C[M,128] = A[M,128] @ W[128,128] ---------
// 3xTF32 (ah*bh + ah*bl + al*bh). ONE 512-thread block per SM, 139KB smem
// holding BOTH W-hi and W-lo (conflict-free GS=136) -> 16 resident warps with
// zero B-side LDG traffic (R6 showed global W-lo makes it L1tex-bound).
// Warp = 16 rows x 64 cols; block = 128 rows x 128 cols.
__global__ void __launch_bounds__(512, 1) k_gemm_tc(
        const float* __restrict__ Aext, int asel, int widx, int csel) {
    const float* __restrict__ A = asel ? g_h : Aext;
    float* __restrict__ C = csel ? g_xr : g_xl;

    extern __shared__ float sw[];          // [2][128][GS]
    float* swh = sw;
    float* swl = sw + 128 * GS;
    {
        const float4* __restrict__ srch = (const float4*)&g_whi[widx][0];
        const float4* __restrict__ srcl = (const float4*)&g_wlo[widx][0];
        int tid = threadIdx.x;
        #pragma unroll
        for (int i = tid; i < 4096; i += 512) {
            int k = i >> 5, c = i & 31;
            *(float4*)&swh[k * GS + c * 4] = srch[i];
            *(float4*)&swl[k * GS + c * 4] = srcl[i];
        }
    }
    __syncthreads();

    int tid = threadIdx.x;
    int warp = tid >> 5, lane = tid & 31;
    int g = lane >> 2, tig = lane & 3;
    int wr = warp >> 1, n0 = (warp & 1) * 64;
    int r0 = blockIdx.x * 128 + wr * 16;
    if (r0 >= NN) return;                  // tail rows % 16 == 0: clean predication

    const float* __restrict__ arow0 = A + (size_t)(r0 + g) * 128;
    const float* __restrict__ arow1 = A + (size_t)(r0 + g + 8) * 128;

    float acc[8][4];
    #pragma unroll
    for (int n = 0; n < 8; n++)
        #pragma unroll
        for (int j = 0; j < 4; j++) acc[n][j] = 0.f;

    #pragma unroll 4
    for (int ks = 0; ks < 16; ks++) {
        int k0 = ks * 8;
        uint32_t ah[4], al[4];
        tf32split(arow0[k0 + tig],     ah[0], al[0]);
        tf32split(arow1[k0 + tig],     ah[1], al[1]);
        tf32split(arow0[k0 + tig + 4], ah[2], al[2]);
        tf32split(arow1[k0 + tig + 4], ah[3], al[3]);

        const float* sh0 = &swh[(k0 + tig) * GS + n0 + g];
        const float* sh1 = &swh[(k0 + tig + 4) * GS + n0 + g];
        const float* sl0 = &swl[(k0 + tig) * GS + n0 + g];
        const float* sl1 = &swl[(k0 + tig + 4) * GS + n0 + g];

        #pragma unroll
        for (int n = 0; n < 8; n++) {
            uint32_t bh0 = __float_as_uint(sh0[n * 8]);
            uint32_t bh1 = __float_as_uint(sh1[n * 8]);
            uint32_t bl0 = __float_as_uint(sl0[n * 8]);
            uint32_t bl1 = __float_as_uint(sl1[n * 8]);
            MMA_TF32(acc[n], ah[0], ah[1], ah[2], ah[3], bh0, bh1);
            MMA_TF32(acc[n], ah[0], ah[1], ah[2], ah[3], bl0, bl1);
            MMA_TF32(acc[n], al[0], al[1], al[2], al[3], bh0, bh1);
        }
    }

    float* c0 = C + (size_t)(r0 + g) * 128 + n0 + 2 * tig;
    float* c1 = C + (size_t)(r0 + g + 8) * 128 + n0 + 2 * tig;
    #pragma unroll
    for (int n = 0; n < 8; n++) {
        *(float2*)&c0[n * 8] = make_float2(acc[n][0], acc[n][1]);
        *(float2*)&c1[n * 8] = make_float2(acc[n][2], acc[n][3]);
    }
}

// ---------------- per-layer init (zero agg + denom) ---------------------------
__global__ void k_init() {
    int i = blockIdx.x * blockDim.x + threadIdx.x;
    if (i < NN * FW / 4) ((float4*)g_agg)[i] = make_float4(0.f, 0.f, 0.f, 0.f);
    if (i < NN * 4) g_denom[i] = 0.f;
}

// ---------------- SINGLE fused edge pass (warp per edge) ---------------------
// logit -> p=exp(logit) -> denom += p ; agg += p * xl[src]  (unnormalized).
// Normalization happens in the per-node epilogue (denom const per dst,head).
__global__ void k_edge(const int* __restrict__ esrc, const int* __restrict__ edst,
                       const float* __restrict__ ew,
                       const float* __restrict__ We, const float* __restrict__ att) {
    int e = (blockIdx.x * blockDim.x + threadIdx.x) >> 5;
    if (e >= EP) return;
    int lane = threadIdx.x & 31;
    int s, d; float w;
    if (e < NE) { s = esrc[e]; d = edst[e]; w = ew[e]; }
    else        { s = d = e - NE; w = g_ewsum * (1.0f / NE); }

    float4 a  = *(const float4*)&g_xl[(size_t)s * 128 + lane * 4];
    float4 b  = *(const float4*)&g_xr[(size_t)d * 128 + lane * 4];
    float4 we = *(const float4*)&We[lane * 4];
    float4 at = *(const float4*)&att[lane * 4];

    float z0 = a.x + b.x + w * we.x; z0 = z0 > 0.f ? z0 : 0.2f * z0;
    float z1 = a.y + b.y + w * we.y; z1 = z1 > 0.f ? z1 : 0.2f * z1;
    float z2 = a.z + b.z + w * we.z; z2 = z2 > 0.f ? z2 : 0.2f * z2;
    float z3 = a.w + b.w + w * we.w; z3 = z3 > 0.f ? z3 : 0.2f * z3;

    float p = z0 * at.x + z1 * at.y + z2 * at.z + z3 * at.w;
    p += __shfl_xor_sync(0xffffffffu, p, 1);
    p += __shfl_xor_sync(0xffffffffu, p, 2);
    p += __shfl_xor_sync(0xffffffffu, p, 4);

    float pe = __expf(p);
    if ((lane & 7) == 0)
        atomicAdd(&g_denom[d * 4 + (lane >> 3)], pe);

    float* dst = &g_agg[(size_t)d * 128 + lane * 4];
    asm volatile("red.global.add.v4.f32 [%0], {%1,%2,%3,%4};"
                 :: "l"(dst), "f"(a.x * pe), "f"(a.y * pe),
                    "f"(a.z * pe), "f"(a.w * pe) : "memory");
}

// ---------------- denom -> reciprocal ----------------------------------------
__global__ void k_inv() {
    int i = blockIdx.x * blockDim.x + threadIdx.x;
    if (i < NN * 4) g_denom[i] = 1.0f / (g_denom[i] + 1e-16f);
}

// ---------------- layer-1 epilogue: normalize + bias + ELU -> g_h ------------
__global__ void k_elu(const float* __restrict__ b1) {
    int idx = blockIdx.x * blockDim.x + threadIdx.x;
    if (idx >= NN * FW) return;
    int n = idx >> 7, h = (idx >> 5) & 3;
    float v = g_agg[idx] * g_denom[n * 4 + h] + b1[idx & 127];
    g_h[idx] = v > 0.f ? v : (__expf(v) - 1.f);
}

// ---------------- layer-2 epilogue: normalize + head-mean + bias -> out ------
__global__ void k_final(const float* __restrict__ b2, float* __restrict__ out) {
    int idx = blockIdx.x * blockDim.x + threadIdx.x;
    if (idx >= NN * 32) return;
    int n = idx >> 5, c = idx & 31;
    size_t base = (size_t)n * 128 + c;
    const float* inv = &g_denom[n * 4];
    float v = 0.25f * (g_agg[base]      * inv[0] + g_agg[base + 32] * inv[1] +
                       g_agg[base + 64] * inv[2] + g_agg[base + 96] * inv[3]);
    out[idx] = v + b2[c];
}

// ---------------- launch ------------------------------------------------------
extern "C" void kernel_launch(void* const* d_in, const int* in_sizes, int n_in,
                              void* d_out, int out_size) {
    const float* x    = (const float*)d_in[0];
    const int*   ei   = (const int*)  d_in[1];
    const float* ew   = (const float*)d_in[2];
    const float* Wl1  = (const float*)d_in[3];
    const float* Wr1  = (const float*)d_in[4];
    const float* We1  = (const float*)d_in[5];
    const float* att1 = (const float*)d_in[6];
    const float* b1   = (const float*)d_in[7];
    const float* Wl2  = (const float*)d_in[8];
    const float* Wr2  = (const float*)d_in[9];
    const float* We2  = (const float*)d_in[10];
    const float* att2 = (const float*)d_in[11];
    const float* b2   = (const float*)d_in[12];
    float* out = (float*)d_out;

    const int* esrc = ei;
    const int* edst = ei + NE;

    const int SMEM_W = 2 * 128 * GS * 4;                // 139,264 B
    cudaFuncSetAttribute(k_gemm_tc,
                         cudaFuncAttributeMaxDynamicSharedMemorySize, SMEM_W);

    const int TC_BLK   = (NN + 127) / 128;              // 391
    const int INIT_BLK = (NN * FW / 4 + 255) / 256;     // 6250
    const int EW_BLK   = (NN * FW + 255) / 256;         // 25000
    const int EDGE_BLK = EP / 8;                        // 206250 (warp/edge)
    const int INV_BLK  = (NN * 4 + 255) / 256;          // 782
    const int FIN_BLK  = (NN * 32 + 255) / 256;         // 6250

    k_zero_scalar<<<1, 1>>>();
    k_ew_reduce<<<448, 256>>>(ew);
    k_wsplit<<<256, 256>>>(Wl1, Wr1, Wl2, Wr2);

    // ---- layer 1 ----
    k_gemm_tc<<<TC_BLK, 512, SMEM_W>>>(x, 0, 0, 0);   // Wl1 -> xl
    k_gemm_tc<<<TC_BLK, 512, SMEM_W>>>(x, 0, 1, 1);   // Wr1 -> xr
    k_init<<<INIT_BLK, 256>>>();
    k_edge<<<EDGE_BLK, 256>>>(esrc, edst, ew, We1, att1);
    k_inv<<<INV_BLK, 256>>>();
    k_elu<<<EW_BLK, 256>>>(b1);

    // ---- layer 2 ----
    k_gemm_tc<<<TC_BLK, 512, SMEM_W>>>(x, 1, 2, 0);   // Wl2 -> xl
    k_gemm_tc<<<TC_BLK, 512, SMEM_W>>>(x, 1, 3, 1);   // Wr2 -> xr
    k_init<<<INIT_BLK, 256>>>();
    k_edge<<<EDGE_BLK, 256>>>(esrc, edst, ew, We2, att2);
    k_inv<<<INV_BLK, 256>>>();
    k_final<<<FIN_BLK, 256>>>(b2, out);
}

// round 11
// speedup vs baseline: 1.3906x; 1.2474x over previous
#include <cuda_runtime.h>
#include <cuda_bf16.h>
#include <cstdint>

#define NN 50000
#define NE 1600000
#define FW 128         // H*C feature width
#define GS 136         // smem stride (floats): banks = 8*tig + g, conflict-free

// ---------------- scratch (device globals; no allocation allowed) ------------
__device__ float g_xl[(size_t)NN * FW];
__device__ float g_xr[(size_t)NN * FW];
__device__ float g_h [(size_t)NN * FW];
__device__ float g_ewsum;
__device__ float g_whi[4][128 * 128];      // tf32-hi of the 4 weight matrices
__device__ float g_wlo[4][128 * 128];      // tf32-lo remainder
__device__ int   g_deg[NN];                // histogram, then fill cursor
__device__ int   g_ptr[NN + 1];            // CSR row offsets (by dst)
__device__ int   g_csr_src[NE];
__device__ float g_csr_w[NE];

// ---------------- edge-weight mean -------------------------------------------
__global__ void k_zero_scalar() { g_ewsum = 0.f; }

__global__ void k_ew_reduce(const float* __restrict__ ew) {
    float s = 0.f;
    int stride = gridDim.x * blockDim.x;
    for (int i = blockIdx.x * blockDim.x + threadIdx.x; i < NE; i += stride)
        s += ew[i];
    #pragma unroll
    for (int o = 16; o; o >>= 1) s += __shfl_xor_sync(0xffffffffu, s, o);
    __shared__ float sm[8];
    int w = threadIdx.x >> 5, l = threadIdx.x & 31;
    if (l == 0) sm[w] = s;
    __syncthreads();
    if (threadIdx.x < 8) {
        s = sm[threadIdx.x];
        #pragma unroll
        for (int o = 4; o; o >>= 1) s += __shfl_xor_sync(0x000000ffu, s, o, 8);
        if (threadIdx.x == 0) atomicAdd(&g_ewsum, s);
    }
}

// ---------------- CSR build (once; reused by both layers) --------------------
__global__ void k_hist_zero() {
    int i = blockIdx.x * blockDim.x + threadIdx.x;
    if (i < NN) g_deg[i] = 0;
}
__global__ void k_hist(const int* __restrict__ edst) {
    int i = blockIdx.x * blockDim.x + threadIdx.x;
    if (i < NE) atomicAdd(&g_deg[edst[i]], 1);
}
// single 256-thread block: exclusive scan g_deg -> g_ptr; g_deg := cursors
__global__ void k_scan() {
    const int CH = (NN + 255) / 256;       // 196
    int tid = threadIdx.x;                 // 0..255
    int lo = tid * CH;
    int hi = lo + CH; if (hi > NN) hi = NN;
    int s = 0;
    for (int i = lo; i < hi; i++) s += g_deg[i];

    __shared__ int wsum[8];
    int lane = tid & 31, w = tid >> 5;
    int v = s;
    #pragma unroll
    for (int o = 1; o < 32; o <<= 1) {
        int t = __shfl_up_sync(0xffffffffu, v, o);
        if (lane >= o) v += t;
    }
    if (lane == 31) wsum[w] = v;
    __syncthreads();
    if (tid == 0) {
        int run = 0;
        #pragma unroll
        for (int i = 0; i < 8; i++) { int t = wsum[i]; wsum[i] = run; run += t; }
    }
    __syncthreads();
    int run = (v - s) + wsum[w];           // exclusive prefix for this thread
    for (int i = lo; i < hi; i++) {
        int d = g_deg[i];
        g_ptr[i] = run;
        run += d;
    }
    if (tid == 0) g_ptr[NN] = NE;          // total degree == edge count
    __syncthreads();
    for (int i = lo; i < hi; i++) g_deg[i] = g_ptr[i];
}
__global__ void k_scatter(const int* __restrict__ esrc, const int* __restrict__ edst,
                          const float* __restrict__ ew) {
    int i = blockIdx.x * blockDim.x + threadIdx.x;
    if (i >= NE) return;
    int d = edst[i];
    int pos = atomicAdd(&g_deg[d], 1);
    g_csr_src[pos] = esrc[i];
    g_csr_w[pos]   = ew[i];
}

// ---------------- tf32 helpers ------------------------------------------------
__device__ __forceinline__ void tf32split(float x, uint32_t& hi, uint32_t& lo) {
    uint32_t h;
    asm("cvt.rna.tf32.f32 %0, %1;" : "=r"(h) : "f"(x));
    float r = x - __uint_as_float(h);
    uint32_t l;
    asm("cvt.rna.tf32.f32 %0, %1;" : "=r"(l) : "f"(r));
    hi = h; lo = l;
}

__global__ void k_wsplit(const float* __restrict__ W0, const float* __restrict__ W1,
                         const float* __restrict__ W2, const float* __restrict__ W3) {
    int i = blockIdx.x * blockDim.x + threadIdx.x;   // 0..65535
    if (i >= 4 * 16384) return;
    int m = i >> 14, j = i & 16383;
    const float* W = (m == 0) ? W0 : (m == 1) ? W1 : (m == 2) ? W2 : W3;
    uint32_t h, l;
    tf32split(W[j], h, l);
    g_whi[m][j] = __uint_as_float(h);
    g_wlo[m][j] = __uint_as_float(l);
}

#define MMA_TF32(ACC, A0, A1, A2, A3, B0, B1)                                   \
    asm volatile("mma.sync.aligned.m16n8k8.row.col.f32.tf32.tf32.f32 "          \
                 "{%0,%1,%2,%3},{%4,%5,%6,%7},{%8,%9},{%0,%1,%2,%3};"           \
                 : "+f"(ACC[0]), "+f"(ACC[1]), "+f"(ACC[2]), "+f"(ACC[3])       \
                 : "r"(A0), "r"(A1), "r"(A2), "r"(A3), "r"(B0), "r"(B1))

// ---------------- tensor-core GEMM: C[M,128] = A[M,128] @ W[128,128] ---------
// 3xTF32 (ah*bh + ah*bl + al*bh). One 512-thread block, 139KB smem holds both
// W-hi and W-lo (conflict-free GS=136); 16 resident warps, zero B-side LDG.
// asel: 0 -> A = Aext (harness input x), 1 -> A = g_h (device global, resolved
// IN DEVICE CODE -- never pass __device__ symbols from host).
__global__ void __launch_bounds__(512, 1) k_gemm_tc(
        const float* __restrict__ Aext, int asel, int widx, int csel) {
    const float* __restrict__ A = asel ? g_h : Aext;
    float* __restrict__ C = csel ? g_xr : g_xl;

    extern __shared__ float sw[];          // [2][128][GS]
    float* swh = sw;
    float* swl = sw + 128 * GS;
    {
        const float4* __restrict__ srch = (const float4*)&g_whi[widx][0];
        const float4* __restrict__ srcl = (const float4*)&g_wlo[widx][0];
        int tid = threadIdx.x;
        #pragma unroll
        for (int i = tid; i < 4096; i += 512) {
            int k = i >> 5, c = i & 31;
            *(float4*)&swh[k * GS + c * 4] = srch[i];
            *(float4*)&swl[k * GS + c * 4] = srcl[i];
        }
    }
    __syncthreads();

    int tid = threadIdx.x;
    int warp = tid >> 5, lane = tid & 31;
    int g = lane >> 2, tig = lane & 3;
    int wr = warp >> 1, n0 = (warp & 1) * 64;
    int r0 = blockIdx.x * 128 + wr * 16;
    if (r0 >= NN) return;                  // tail rows % 16 == 0: clean predication

    const float* __restrict__ arow0 = A + (size_t)(r0 + g) * 128;
    const float* __restrict__ arow1 = A + (size_t)(r0 + g + 8) * 128;

    float acc[8][4];
    #pragma unroll
    for (int n = 0; n < 8; n++)
        #pragma unroll
        for (int j = 0; j < 4; j++) acc[n][j] = 0.f;

    #pragma unroll 4
    for (int ks = 0; ks < 16; ks++) {
        int k0 = ks * 8;
        uint32_t ah[4], al[4];
        tf32split(arow0[k0 + tig],     ah[0], al[0]);
        tf32split(arow1[k0 + tig],     ah[1], al[1]);
        tf32split(arow0[k0 + tig + 4], ah[2], al[2]);
        tf32split(arow1[k0 + tig + 4], ah[3], al[3]);

        const float* sh0 = &swh[(k0 + tig) * GS + n0 + g];
        const float* sh1 = &swh[(k0 + tig + 4) * GS + n0 + g];
        const float* sl0 = &swl[(k0 + tig) * GS + n0 + g];
        const float* sl1 = &swl[(k0 + tig + 4) * GS + n0 + g];

        #pragma unroll
        for (int n = 0; n < 8; n++) {
            uint32_t bh0 = __float_as_uint(sh0[n * 8]);
            uint32_t bh1 = __float_as_uint(sh1[n * 8]);
            uint32_t bl0 = __float_as_uint(sl0[n * 8]);
            uint32_t bl1 = __float_as_uint(sl1[n * 8]);
            MMA_TF32(acc[n], ah[0], ah[1], ah[2], ah[3], bh0, bh1);
            MMA_TF32(acc[n], ah[0], ah[1], ah[2], ah[3], bl0, bl1);
            MMA_TF32(acc[n], al[0], al[1], al[2], al[3], bh0, bh1);
        }
    }

    float* c0 = C + (size_t)(r0 + g) * 128 + n0 + 2 * tig;
    float* c1 = C + (size_t)(r0 + g + 8) * 128 + n0 + 2 * tig;
    #pragma unroll
    for (int n = 0; n < 8; n++) {
        *(float2*)&c0[n * 8] = make_float2(acc[n][0], acc[n][1]);
        *(float2*)&c1[n * 8] = make_float2(acc[n][2], acc[n][3]);
    }
}

// ---------------- node-centric fused layers (warp per node) ------------------
// Shared mainloop: xr[d], We, att register-resident; gather only xl[src];
// p=exp(logit) accumulated into registers. No atomics, epilogue fused.
__device__ __forceinline__ void node_core(int n, int lane,
        const float* __restrict__ We, const float* __restrict__ att,
        float4& acc, float& dsum) {
    float4 b  = *(const float4*)&g_xr[(size_t)n * 128 + lane * 4];
    float4 we = *(const float4*)&We[lane * 4];
    float4 at = *(const float4*)&att[lane * 4];

    acc = make_float4(0.f, 0.f, 0.f, 0.f);
    dsum = 0.f;

    int beg = g_ptr[n], end = g_ptr[n + 1];
    float wmean = g_ewsum * (1.0f / NE);

    for (int i = beg; i <= end; i++) {
        int s; float w;
        if (i < end) { s = g_csr_src[i]; w = g_csr_w[i]; }
        else         { s = n; w = wmean; }               // self loop
        float4 a = *(const float4*)&g_xl[(size_t)s * 128 + lane * 4];

        float z0 = a.x + b.x + w * we.x; z0 = z0 > 0.f ? z0 : 0.2f * z0;
        float z1 = a.y + b.y + w * we.y; z1 = z1 > 0.f ? z1 : 0.2f * z1;
        float z2 = a.z + b.z + w * we.z; z2 = z2 > 0.f ? z2 : 0.2f * z2;
        float z3 = a.w + b.w + w * we.w; z3 = z3 > 0.f ? z3 : 0.2f * z3;

        float p = z0 * at.x + z1 * at.y + z2 * at.z + z3 * at.w;
        p += __shfl_xor_sync(0xffffffffu, p, 1);
        p += __shfl_xor_sync(0xffffffffu, p, 2);
        p += __shfl_xor_sync(0xffffffffu, p, 4);

        float pe = __expf(p);
        acc.x += pe * a.x; acc.y += pe * a.y;
        acc.z += pe * a.z; acc.w += pe * a.w;
        dsum += pe;
    }
}

// layer 1: writes g_h DIRECTLY (device-side symbol access; no host-passed ptr)
__global__ void k_node1(const float* __restrict__ We, const float* __restrict__ att,
                        const float* __restrict__ bias) {
    int n = (blockIdx.x * blockDim.x + threadIdx.x) >> 5;
    if (n >= NN) return;
    int lane = threadIdx.x & 31;
    float4 acc; float dsum;
    node_core(n, lane, We, att, acc, dsum);
    float inv = 1.0f / (dsum + 1e-16f);

    float4 bi = *(const float4*)&bias[lane * 4];
    float v0 = acc.x * inv + bi.x;
    float v1 = acc.y * inv + bi.y;
    float v2 = acc.z * inv + bi.z;
    float v3 = acc.w * inv + bi.w;
    v0 = v0 > 0.f ? v0 : (__expf(v0) - 1.f);
    v1 = v1 > 0.f ? v1 : (__expf(v1) - 1.f);
    v2 = v2 > 0.f ? v2 : (__expf(v2) - 1.f);
    v3 = v3 > 0.f ? v3 : (__expf(v3) - 1.f);
    *(float4*)&g_h[(size_t)n * 128 + lane * 4] = make_float4(v0, v1, v2, v3);
}

// layer 2: writes harness-provided d_out (valid device pointer argument)
__global__ void k_node2(const float* __restrict__ We, const float* __restrict__ att,
                        const float* __restrict__ bias, float* __restrict__ out) {
    int n = (blockIdx.x * blockDim.x + threadIdx.x) >> 5;
    if (n >= NN) return;
    int lane = threadIdx.x & 31;
    float4 acc; float dsum;
    node_core(n, lane, We, att, acc, dsum);
    float inv = 1.0f / (dsum + 1e-16f);

    float v0 = acc.x * inv, v1 = acc.y * inv, v2 = acc.z * inv, v3 = acc.w * inv;
    // mean over heads: lanes {c, c+8, c+16, c+24} hold the same channels
    #pragma unroll
    for (int o = 8; o <= 16; o <<= 1) {
        v0 += __shfl_xor_sync(0xffffffffu, v0, o);
        v1 += __shfl_xor_sync(0xffffffffu, v1, o);
        v2 += __shfl_xor_sync(0xffffffffu, v2, o);
        v3 += __shfl_xor_sync(0xffffffffu, v3, o);
    }
    if (lane < 8) {
        float4 bi = *(const float4*)&bias[lane * 4];
        *(float4*)&out[(size_t)n * 32 + lane * 4] =
            make_float4(0.25f * v0 + bi.x, 0.25f * v1 + bi.y,
                        0.25f * v2 + bi.z, 0.25f * v3 + bi.w);
    }
}

// ---------------- launch ------------------------------------------------------
extern "C" void kernel_launch(void* const* d_in, const int* in_sizes, int n_in,
                              void* d_out, int out_size) {
    const float* x    = (const float*)d_in[0];
    const int*   ei   = (const int*)  d_in[1];
    const float* ew   = (const float*)d_in[2];
    const float* Wl1  = (const float*)d_in[3];
    const float* Wr1  = (const float*)d_in[4];
    const float* We1  = (const float*)d_in[5];
    const float* att1 = (const float*)d_in[6];
    const float* b1   = (const float*)d_in[7];
    const float* Wl2  = (const float*)d_in[8];
    const float* Wr2  = (const float*)d_in[9];
    const float* We2  = (const float*)d_in[10];
    const float* att2 = (const float*)d_in[11];
    const float* b2   = (const float*)d_in[12];
    float* out = (float*)d_out;

    const int* esrc = ei;
    const int* edst = ei + NE;

    const int SMEM_W = 2 * 128 * GS * 4;                // 139,264 B
    cudaFuncSetAttribute(k_gemm_tc,
                         cudaFuncAttributeMaxDynamicSharedMemorySize, SMEM_W);

    const int TC_BLK   = (NN + 127) / 128;              // 391
    const int NODE_BLK = (NN * 32 + 255) / 256;         // 6250 (warp per node)
    const int NE_BLK   = (NE + 255) / 256;              // 6250
    const int NN_BLK   = (NN + 255) / 256;              // 196

    k_zero_scalar<<<1, 1>>>();
    k_ew_reduce<<<448, 256>>>(ew);
    k_wsplit<<<256, 256>>>(Wl1, Wr1, Wl2, Wr2);

    // CSR build (by dst), reused by both layers
    k_hist_zero<<<NN_BLK, 256>>>();
    k_hist<<<NE_BLK, 256>>>(edst);
    k_scan<<<1, 256>>>();
    k_scatter<<<NE_BLK, 256>>>(esrc, edst, ew);

    // ---- layer 1 ----
    k_gemm_tc<<<TC_BLK, 512, SMEM_W>>>(x, 0, 0, 0);   // Wl1 -> xl
    k_gemm_tc<<<TC_BLK, 512, SMEM_W>>>(x, 0, 1, 1);   // Wr1 -> xr
    k_node1<<<NODE_BLK, 256>>>(We1, att1, b1);

    // ---- layer 2 ----
    k_gemm_tc<<<TC_BLK, 512, SMEM_W>>>(x, 1, 2, 0);   // Wl2 -> xl
    k_gemm_tc<<<TC_BLK, 512, SMEM_W>>>(x, 1, 3, 1);   // Wr2 -> xr
    k_node2<<<NODE_BLK, 256>>>(We2, att2, b2, out);
}

// round 13
// speedup vs baseline: 1.5209x; 1.0937x over previous
#include <cuda_runtime.h>
#include <cuda_bf16.h>
#include <cstdint>

#define NN 50000
#define NE 1600000
#define FW 128         // H*C feature width
#define GS 136         // smem stride (floats): banks = 8*tig + g, conflict-free

// ---------------- scratch (device globals; no allocation allowed) ------------
__device__ float g_xl[(size_t)NN * FW];
__device__ float g_xr[(size_t)NN * FW];
__device__ float g_h [(size_t)NN * FW];
__device__ float g_ewsum;
__device__ float g_whi[4][128 * 128];      // tf32-hi of the 4 weight matrices
__device__ float g_wlo[4][128 * 128];      // tf32-lo remainder
__device__ int   g_deg[NN];                // histogram, then fill cursor
__device__ int   g_ptr[NN + 1];            // CSR row offsets (by dst)
__device__ int   g_csr_src[NE];
__device__ float g_csr_w[NE];

// ---------------- edge-weight mean -------------------------------------------
__global__ void k_zero_scalar() { g_ewsum = 0.f; }

__global__ void k_ew_reduce(const float* __restrict__ ew) {
    float s = 0.f;
    int stride = gridDim.x * blockDim.x;
    for (int i = blockIdx.x * blockDim.x + threadIdx.x; i < NE; i += stride)
        s += ew[i];
    #pragma unroll
    for (int o = 16; o; o >>= 1) s += __shfl_xor_sync(0xffffffffu, s, o);
    __shared__ float sm[8];
    int w = threadIdx.x >> 5, l = threadIdx.x & 31;
    if (l == 0) sm[w] = s;
    __syncthreads();
    if (threadIdx.x < 8) {
        s = sm[threadIdx.x];
        #pragma unroll
        for (int o = 4; o; o >>= 1) s += __shfl_xor_sync(0x000000ffu, s, o, 8);
        if (threadIdx.x == 0) atomicAdd(&g_ewsum, s);
    }
}

// ---------------- CSR build (once; reused by both layers) --------------------
__global__ void k_hist_zero() {
    int i = blockIdx.x * blockDim.x + threadIdx.x;
    if (i < NN) g_deg[i] = 0;
}
__global__ void k_hist(const int* __restrict__ edst) {
    int i = blockIdx.x * blockDim.x + threadIdx.x;
    if (i < NE) atomicAdd(&g_deg[edst[i]], 1);
}
// single 256-thread block: exclusive scan g_deg -> g_ptr; g_deg := cursors
__global__ void k_scan() {
    const int CH = (NN + 255) / 256;       // 196
    int tid = threadIdx.x;                 // 0..255
    int lo = tid * CH;
    int hi = lo + CH; if (hi > NN) hi = NN;
    int s = 0;
    for (int i = lo; i < hi; i++) s += g_deg[i];

    __shared__ int wsum[8];
    int lane = tid & 31, w = tid >> 5;
    int v = s;
    #pragma unroll
    for (int o = 1; o < 32; o <<= 1) {
        int t = __shfl_up_sync(0xffffffffu, v, o);
        if (lane >= o) v += t;
    }
    if (lane == 31) wsum[w] = v;
    __syncthreads();
    if (tid == 0) {
        int run = 0;
        #pragma unroll
        for (int i = 0; i < 8; i++) { int t = wsum[i]; wsum[i] = run; run += t; }
    }
    __syncthreads();
    int run = (v - s) + wsum[w];           // exclusive prefix for this thread
    for (int i = lo; i < hi; i++) {
        int d = g_deg[i];
        g_ptr[i] = run;
        run += d;
    }
    if (tid == 0) g_ptr[NN] = NE;          // total degree == edge count
    __syncthreads();
    for (int i = lo; i < hi; i++) g_deg[i] = g_ptr[i];
}
__global__ void k_scatter(const int* __restrict__ esrc, const int* __restrict__ edst,
                          const float* __restrict__ ew) {
    int i = blockIdx.x * blockDim.x + threadIdx.x;
    if (i >= NE) return;
    int d = edst[i];
    int pos = atomicAdd(&g_deg[d], 1);
    g_csr_src[pos] = esrc[i];
    g_csr_w[pos]   = ew[i];
}

// ---------------- tf32 helpers ------------------------------------------------
__device__ __forceinline__ void tf32split(float x, uint32_t& hi, uint32_t& lo) {
    uint32_t h;
    asm("cvt.rna.tf32.f32 %0, %1;" : "=r"(h) : "f"(x));
    float r = x - __uint_as_float(h);
    uint32_t l;
    asm("cvt.rna.tf32.f32 %0, %1;" : "=r"(l) : "f"(r));
    hi = h; lo = l;
}

__global__ void k_wsplit(const float* __restrict__ W0, const float* __restrict__ W1,
                         const float* __restrict__ W2, const float* __restrict__ W3) {
    int i = blockIdx.x * blockDim.x + threadIdx.x;   // 0..65535
    if (i >= 4 * 16384) return;
    int m = i >> 14, j = i & 16383;
    const float* W = (m == 0) ? W0 : (m == 1) ? W1 : (m == 2) ? W2 : W3;
    uint32_t h, l;
    tf32split(W[j], h, l);
    g_whi[m][j] = __uint_as_float(h);
    g_wlo[m][j] = __uint_as_float(l);
}

#define MMA_TF32(ACC, A0, A1, A2, A3, B0, B1)                                   \
    asm volatile("mma.sync.aligned.m16n8k8.row.col.f32.tf32.tf32.f32 "          \
                 "{%0,%1,%2,%3},{%4,%5,%6,%7},{%8,%9},{%0,%1,%2,%3};"           \
                 : "+f"(ACC[0]), "+f"(ACC[1]), "+f"(ACC[2]), "+f"(ACC[3])       \
                 : "r"(A0), "r"(A1), "r"(A2), "r"(A3), "r"(B0), "r"(B1))

// ---------------- tensor-core GEMM: C[M,128] = A[M,128] @ W[128,128] ---------
// 3xTF32 (ah*bh + ah*bl + al*bh). One 512-thread block, 139KB smem holds both
// W-hi and W-lo (conflict-free GS=136); 16 resident warps, zero B-side LDG.
__global__ void __launch_bounds__(512, 1) k_gemm_tc(
        const float* __restrict__ Aext, int asel, int widx, int csel) {
    const float* __restrict__ A = asel ? g_h : Aext;
    float* __restrict__ C = csel ? g_xr : g_xl;

    extern __shared__ float sw[];          // [2][128][GS]
    float* swh = sw;
    float* swl = sw + 128 * GS;
    {
        const float4* __restrict__ srch = (const float4*)&g_whi[widx][0];
        const float4* __restrict__ srcl = (const float4*)&g_wlo[widx][0];
        int tid = threadIdx.x;
        #pragma unroll
        for (int i = tid; i < 4096; i += 512) {
            int k = i >> 5, c = i & 31;
            *(float4*)&swh[k * GS + c * 4] = srch[i];
            *(float4*)&swl[k * GS + c * 4] = srcl[i];
        }
    }
    __syncthreads();

    int tid = threadIdx.x;
    int warp = tid >> 5, lane = tid & 31;
    int g = lane >> 2, tig = lane & 3;
    int wr = warp >> 1, n0 = (warp & 1) * 64;
    int r0 = blockIdx.x * 128 + wr * 16;
    if (r0 >= NN) return;                  // tail rows % 16 == 0: clean predication

    const float* __restrict__ arow0 = A + (size_t)(r0 + g) * 128;
    const float* __restrict__ arow1 = A + (size_t)(r0 + g + 8) * 128;

    float acc[8][4];
    #pragma unroll
    for (int n = 0; n < 8; n++)
        #pragma unroll
        for (int j = 0; j < 4; j++) acc[n][j] = 0.f;

    #pragma unroll 4
    for (int ks = 0; ks < 16; ks++) {
        int k0 = ks * 8;
        uint32_t ah[4], al[4];
        tf32split(arow0[k0 + tig],     ah[0], al[0]);
        tf32split(arow1[k0 + tig],     ah[1], al[1]);
        tf32split(arow0[k0 + tig + 4], ah[2], al[2]);
        tf32split(arow1[k0 + tig + 4], ah[3], al[3]);

        const float* sh0 = &swh[(k0 + tig) * GS + n0 + g];
        const float* sh1 = &swh[(k0 + tig + 4) * GS + n0 + g];
        const float* sl0 = &swl[(k0 + tig) * GS + n0 + g];
        const float* sl1 = &swl[(k0 + tig + 4) * GS + n0 + g];

        #pragma unroll
        for (int n = 0; n < 8; n++) {
            uint32_t bh0 = __float_as_uint(sh0[n * 8]);
            uint32_t bh1 = __float_as_uint(sh1[n * 8]);
            uint32_t bl0 = __float_as_uint(sl0[n * 8]);
            uint32_t bl1 = __float_as_uint(sl1[n * 8]);
            MMA_TF32(acc[n], ah[0], ah[1], ah[2], ah[3], bh0, bh1);
            MMA_TF32(acc[n], ah[0], ah[1], ah[2], ah[3], bl0, bl1);
            MMA_TF32(acc[n], al[0], al[1], al[2], al[3], bh0, bh1);
        }
    }

    float* c0 = C + (size_t)(r0 + g) * 128 + n0 + 2 * tig;
    float* c1 = C + (size_t)(r0 + g + 8) * 128 + n0 + 2 * tig;
    #pragma unroll
    for (int n = 0; n < 8; n++) {
        *(float2*)&c0[n * 8] = make_float2(acc[n][0], acc[n][1]);
        *(float2*)&c1[n * 8] = make_float2(acc[n][2], acc[n][3]);
    }
}

// ---------------- node-centric fused layers (warp per node) ------------------
// Unroll-by-4 edge loop: 4 independent CSR loads + 4 independent xl gathers
// (MLP=4) + 4 interleavable z/shfl/exp chains. Self-loop hoisted out.

#define EDGE_ZP(A, W, P)                                                        \
    {                                                                           \
        float z0 = (A).x + b.x + (W) * we.x; z0 = z0 > 0.f ? z0 : 0.2f * z0;   \
        float z1 = (A).y + b.y + (W) * we.y; z1 = z1 > 0.f ? z1 : 0.2f * z1;   \
        float z2 = (A).z + b.z + (W) * we.z; z2 = z2 > 0.f ? z2 : 0.2f * z2;   \
        float z3 = (A).w + b.w + (W) * we.w; z3 = z3 > 0.f ? z3 : 0.2f * z3;   \
        (P) = z0 * at.x + z1 * at.y + z2 * at.z + z3 * at.w;                    \
    }

__device__ __forceinline__ void node_core(int n, int lane,
        const float* __restrict__ We, const float* __restrict__ att,
        float4& acc, float& dsum) {
    float4 b  = *(const float4*)&g_xr[(size_t)n * 128 + lane * 4];
    float4 we = *(const float4*)&We[lane * 4];
    float4 at = *(const float4*)&att[lane * 4];

    // self loop first (hoisted out of the edge loop)
    {
        float4 a = *(const float4*)&g_xl[(size_t)n * 128 + lane * 4];
        float p;
        EDGE_ZP(a, g_ewsum * (1.0f / NE), p);
        p += __shfl_xor_sync(0xffffffffu, p, 1);
        p += __shfl_xor_sync(0xffffffffu, p, 2);
        p += __shfl_xor_sync(0xffffffffu, p, 4);
        float pe = __expf(p);
        acc = make_float4(pe * a.x, pe * a.y, pe * a.z, pe * a.w);
        dsum = pe;
    }

    int beg = g_ptr[n], end = g_ptr[n + 1];
    int i = beg;

    for (; i + 4 <= end; i += 4) {
        int   s0 = g_csr_src[i],     s1 = g_csr_src[i + 1];
        int   s2 = g_csr_src[i + 2], s3 = g_csr_src[i + 3];
        float w0 = g_csr_w[i],       w1 = g_csr_w[i + 1];
        float w2 = g_csr_w[i + 2],   w3 = g_csr_w[i + 3];

        float4 a0 = *(const float4*)&g_xl[(size_t)s0 * 128 + lane * 4];
        float4 a1 = *(const float4*)&g_xl[(size_t)s1 * 128 + lane * 4];
        float4 a2 = *(const float4*)&g_xl[(size_t)s2 * 128 + lane * 4];
        float4 a3 = *(const float4*)&g_xl[(size_t)s3 * 128 + lane * 4];

        float p0, p1, p2, p3;
        EDGE_ZP(a0, w0, p0); EDGE_ZP(a1, w1, p1);
        EDGE_ZP(a2, w2, p2); EDGE_ZP(a3, w3, p3);

        // 4 independent 3-shfl chains — scheduler can overlap them
        p0 += __shfl_xor_sync(0xffffffffu, p0, 1);
        p1 += __shfl_xor_sync(0xffffffffu, p1, 1);
        p2 += __shfl_xor_sync(0xffffffffu, p2, 1);
        p3 += __shfl_xor_sync(0xffffffffu, p3, 1);
        p0 += __shfl_xor_sync(0xffffffffu, p0, 2);
        p1 += __shfl_xor_sync(0xffffffffu, p1, 2);
        p2 += __shfl_xor_sync(0xffffffffu, p2, 2);
        p3 += __shfl_xor_sync(0xffffffffu, p3, 2);
        p0 += __shfl_xor_sync(0xffffffffu, p0, 4);
        p1 += __shfl_xor_sync(0xffffffffu, p1, 4);
        p2 += __shfl_xor_sync(0xffffffffu, p2, 4);
        p3 += __shfl_xor_sync(0xffffffffu, p3, 4);

        float e0 = __expf(p0), e1 = __expf(p1);
        float e2 = __expf(p2), e3 = __expf(p3);

        acc.x += e0 * a0.x + e1 * a1.x + e2 * a2.x + e3 * a3.x;
        acc.y += e0 * a0.y + e1 * a1.y + e2 * a2.y + e3 * a3.y;
        acc.z += e0 * a0.z + e1 * a1.z + e2 * a2.z + e3 * a3.z;
        acc.w += e0 * a0.w + e1 * a1.w + e2 * a2.w + e3 * a3.w;
        dsum += (e0 + e1) + (e2 + e3);
    }

    for (; i < end; i++) {
        int s = g_csr_src[i];
        float w = g_csr_w[i];
        float4 a = *(const float4*)&g_xl[(size_t)s * 128 + lane * 4];
        float p;
        EDGE_ZP(a, w, p);
        p += __shfl_xor_sync(0xffffffffu, p, 1);
        p += __shfl_xor_sync(0xffffffffu, p, 2);
        p += __shfl_xor_sync(0xffffffffu, p, 4);
        float pe = __expf(p);
        acc.x += pe * a.x; acc.y += pe * a.y;
        acc.z += pe * a.z; acc.w += pe * a.w;
        dsum += pe;
    }
}

// layer 1: writes g_h DIRECTLY (device-side symbol access; no host-passed ptr)
__global__ void k_node1(const float* __restrict__ We, const float* __restrict__ att,
                        const float* __restrict__ bias) {
    int n = (blockIdx.x * blockDim.x + threadIdx.x) >> 5;
    if (n >= NN) return;
    int lane = threadIdx.x & 31;
    float4 acc; float dsum;
    node_core(n, lane, We, att, acc, dsum);
    float inv = 1.0f / (dsum + 1e-16f);

    float4 bi = *(const float4*)&bias[lane * 4];
    float v0 = acc.x * inv + bi.x;
    float v1 = acc.y * inv + bi.y;
    float v2 = acc.z * inv + bi.z;
    float v3 = acc.w * inv + bi.w;
    v0 = v0 > 0.f ? v0 : (__expf(v0) - 1.f);
    v1 = v1 > 0.f ? v1 : (__expf(v1) - 1.f);
    v2 = v2 > 0.f ? v2 : (__expf(v2) - 1.f);
    v3 = v3 > 0.f ? v3 : (__expf(v3) - 1.f);
    *(float4*)&g_h[(size_t)n * 128 + lane * 4] = make_float4(v0, v1, v2, v3);
}

// layer 2: writes harness-provided d_out (valid device pointer argument)
__global__ void k_node2(const float* __restrict__ We, const float* __restrict__ att,
                        const float* __restrict__ bias, float* __restrict__ out) {
    int n = (blockIdx.x * blockDim.x + threadIdx.x) >> 5;
    if (n >= NN) return;
    int lane = threadIdx.x & 31;
    float4 acc; float dsum;
    node_core(n, lane, We, att, acc, dsum);
    float inv = 1.0f / (dsum + 1e-16f);

    float v0 = acc.x * inv, v1 = acc.y * inv, v2 = acc.z * inv, v3 = acc.w * inv;
    // mean over heads: lanes {c, c+8, c+16, c+24} hold the same channels
    #pragma unroll
    for (int o = 8; o <= 16; o <<= 1) {
        v0 += __shfl_xor_sync(0xffffffffu, v0, o);
        v1 += __shfl_xor_sync(0xffffffffu, v1, o);
        v2 += __shfl_xor_sync(0xffffffffu, v2, o);
        v3 += __shfl_xor_sync(0xffffffffu, v3, o);
    }
    if (lane < 8) {
        float4 bi = *(const float4*)&bias[lane * 4];
        *(float4*)&out[(size_t)n * 32 + lane * 4] =
            make_float4(0.25f * v0 + bi.x, 0.25f * v1 + bi.y,
                        0.25f * v2 + bi.z, 0.25f * v3 + bi.w);
    }
}

// ---------------- launch ------------------------------------------------------
extern "C" void kernel_launch(void* const* d_in, const int* in_sizes, int n_in,
                              void* d_out, int out_size) {
    const float* x    = (const float*)d_in[0];
    const int*   ei   = (const int*)  d_in[1];
    const float* ew   = (const float*)d_in[2];
    const float* Wl1  = (const float*)d_in[3];
    const float* Wr1  = (const float*)d_in[4];
    const float* We1  = (const float*)d_in[5];
    const float* att1 = (const float*)d_in[6];
    const float* b1   = (const float*)d_in[7];
    const float* Wl2  = (const float*)d_in[8];
    const float* Wr2  = (const float*)d_in[9];
    const float* We2  = (const float*)d_in[10];
    const float* att2 = (const float*)d_in[11];
    const float* b2   = (const float*)d_in[12];
    float* out = (float*)d_out;

    const int* esrc = ei;
    const int* edst = ei + NE;

    const int SMEM_W = 2 * 128 * GS * 4;                // 139,264 B
    cudaFuncSetAttribute(k_gemm_tc,
                         cudaFuncAttributeMaxDynamicSharedMemorySize, SMEM_W);

    const int TC_BLK   = (NN + 127) / 128;              // 391
    const int NODE_BLK = (NN * 32 + 255) / 256;         // 6250 (warp per node)
    const int NE_BLK   = (NE + 255) / 256;              // 6250
    const int NN_BLK   = (NN + 255) / 256;              // 196

    k_zero_scalar<<<1, 1>>>();
    k_ew_reduce<<<448, 256>>>(ew);
    k_wsplit<<<256, 256>>>(Wl1, Wr1, Wl2, Wr2);

    // CSR build (by dst), reused by both layers
    k_hist_zero<<<NN_BLK, 256>>>();
    k_hist<<<NE_BLK, 256>>>(edst);
    k_scan<<<1, 256>>>();
    k_scatter<<<NE_BLK, 256>>>(esrc, edst, ew);

    // ---- layer 1 ----
    k_gemm_tc<<<TC_BLK, 512, SMEM_W>>>(x, 0, 0, 0);   // Wl1 -> xl
    k_gemm_tc<<<TC_BLK, 512, SMEM_W>>>(x, 0, 1, 1);   // Wr1 -> xr
    k_node1<<<NODE_BLK, 256>>>(We1, att1, b1);

    // ---- layer 2 ----
    k_gemm_tc<<<TC_BLK, 512, SMEM_W>>>(x, 1, 2, 0);   // Wl2 -> xl
    k_gemm_tc<<<TC_BLK, 512, SMEM_W>>>(x, 1, 3, 1);   // Wr2 -> xr
    k_node2<<<NODE_BLK, 256>>>(We2, att2, b2, out);
}

// round 15
// speedup vs baseline: 1.5511x; 1.0198x over previous
#include <cuda_runtime.h>
#include <cuda_bf16.h>
#include <cstdint>

#define NN 50000
#define NE 1600000
#define FW 128         // H*C feature width
#define GS 136         // smem stride (floats): banks = 8*tig + g, conflict-free

// ---------------- scratch (device globals; no allocation allowed) ------------
__device__ float    g_xl[(size_t)NN * FW];
__device__ float    g_xr[(size_t)NN * FW];
__device__ float    g_h [(size_t)NN * FW];
__device__ float    g_ewsum;
__device__ float    g_whi [4][128 * 128];  // tf32-hi of the 4 weight matrices
__device__ uint16_t g_wlo16[4][128 * 128]; // bf16 lo remainder (expands to tf32)
__device__ int      g_deg[NN];             // histogram, then fill cursor
__device__ int      g_ptr[NN + 1];         // CSR row offsets (by dst)
__device__ int      g_csr_src[NE];
__device__ float    g_csr_w[NE];

// ---------------- edge-weight mean -------------------------------------------
__global__ void k_ew_reduce(const float* __restrict__ ew) {
    float s = 0.f;
    int stride = gridDim.x * blockDim.x;
    for (int i = blockIdx.x * blockDim.x + threadIdx.x; i < NE; i += stride)
        s += ew[i];
    #pragma unroll
    for (int o = 16; o; o >>= 1) s += __shfl_xor_sync(0xffffffffu, s, o);
    __shared__ float sm[8];
    int w = threadIdx.x >> 5, l = threadIdx.x & 31;
    if (l == 0) sm[w] = s;
    __syncthreads();
    if (threadIdx.x < 8) {
        s = sm[threadIdx.x];
        #pragma unroll
        for (int o = 4; o; o >>= 1) s += __shfl_xor_sync(0x000000ffu, s, o, 8);
        if (threadIdx.x == 0) atomicAdd(&g_ewsum, s);
    }
}

// ---------------- CSR build (once; reused by both layers) --------------------
__global__ void k_hist_zero() {
    int i = blockIdx.x * blockDim.x + threadIdx.x;
    if (i < NN) g_deg[i] = 0;
    if (i == 0) g_ewsum = 0.f;
}
__global__ void k_hist(const int* __restrict__ edst) {
    int i = blockIdx.x * blockDim.x + threadIdx.x;
    if (i < NE) atomicAdd(&g_deg[edst[i]], 1);
}
// single 256-thread block: exclusive scan g_deg -> g_ptr; g_deg := cursors
__global__ void k_scan() {
    const int CH = (NN + 255) / 256;       // 196
    int tid = threadIdx.x;                 // 0..255
    int lo = tid * CH;
    int hi = lo + CH; if (hi > NN) hi = NN;
    int s = 0;
    for (int i = lo; i < hi; i++) s += g_deg[i];

    __shared__ int wsum[8];
    int lane = tid & 31, w = tid >> 5;
    int v = s;
    #pragma unroll
    for (int o = 1; o < 32; o <<= 1) {
        int t = __shfl_up_sync(0xffffffffu, v, o);
        if (lane >= o) v += t;
    }
    if (lane == 31) wsum[w] = v;
    __syncthreads();
    if (tid == 0) {
        int run = 0;
        #pragma unroll
        for (int i = 0; i < 8; i++) { int t = wsum[i]; wsum[i] = run; run += t; }
    }
    __syncthreads();
    int run = (v - s) + wsum[w];           // exclusive prefix for this thread
    for (int i = lo; i < hi; i++) {
        int d = g_deg[i];
        g_ptr[i] = run;
        run += d;
    }
    if (tid == 0) g_ptr[NN] = NE;          // total degree == edge count
    __syncthreads();
    for (int i = lo; i < hi; i++) g_deg[i] = g_ptr[i];
}
__global__ void k_scatter(const int* __restrict__ esrc, const int* __restrict__ edst,
                          const float* __restrict__ ew) {
    int i = blockIdx.x * blockDim.x + threadIdx.x;
    if (i >= NE) return;
    int d = edst[i];
    int pos = atomicAdd(&g_deg[d], 1);
    g_csr_src[pos] = esrc[i];
    g_csr_w[pos]   = ew[i];
}

// ---------------- tf32 split: hi tf32 (fp32 slot), lo bf16 -------------------
__global__ void k_wsplit(const float* __restrict__ W0, const float* __restrict__ W1,
                         const float* __restrict__ W2, const float* __restrict__ W3) {
    int i = blockIdx.x * blockDim.x + threadIdx.x;   // 0..65535
    if (i >= 4 * 16384) return;
    int m = i >> 14, j = i & 16383;
    const float* W = (m == 0) ? W0 : (m == 1) ? W1 : (m == 2) ? W2 : W3;
    float x = W[j];
    uint32_t h;
    asm("cvt.rna.tf32.f32 %0, %1;" : "=r"(h) : "f"(x));
    float r = x - __uint_as_float(h);
    g_whi[m][j]   = __uint_as_float(h);
    g_wlo16[m][j] = __bfloat16_as_ushort(__float2bfloat16(r));
}

__device__ __forceinline__ void tf32split(float x, uint32_t& hi, uint32_t& lo) {
    uint32_t h;
    asm("cvt.rna.tf32.f32 %0, %1;" : "=r"(h) : "f"(x));
    float r = x - __uint_as_float(h);
    uint32_t l;
    asm("cvt.rna.tf32.f32 %0, %1;" : "=r"(l) : "f"(r));
    hi = h; lo = l;
}

#define MMA_TF32(ACC, A0, A1, A2, A3, B0, B1)                                   \
    asm volatile("mma.sync.aligned.m16n8k8.row.col.f32.tf32.tf32.f32 "          \
                 "{%0,%1,%2,%3},{%4,%5,%6,%7},{%8,%9},{%0,%1,%2,%3};"           \
                 : "+f"(ACC[0]), "+f"(ACC[1]), "+f"(ACC[2]), "+f"(ACC[3])       \
                 : "r"(A0), "r"(A1), "r"(A2), "r"(A3), "r"(B0), "r"(B1))

// ---------------- merged dual GEMM: [xl|xr] = A @ [Wl|Wr] --------------------
// 3xTF32; per layer ONE launch. 512 thr = 16 warps = 8 row-groups x 2 matrices;
// warp = 16 rows x 128 cols of ONE output -> A-side splits amortized over 2x
// MMA work. smem: Wl-hi,Wr-hi fp32 + Wl-lo,Wr-lo bf16 (expand <<16 to tf32).
#define SMEM_G2 (2 * 128 * GS * 4 + 2 * 128 * GS * 2)   // 208,896 B
__global__ void __launch_bounds__(512, 1) k_gemm2(
        const float* __restrict__ Aext, int asel, int layer) {
    const float* __restrict__ A = asel ? g_h : Aext;

    extern __shared__ float sw[];
    float* swh0 = sw;                        // Wl hi [128][GS]
    float* swh1 = sw + 128 * GS;             // Wr hi
    uint16_t* sl0 = (uint16_t*)(sw + 2 * 128 * GS);      // Wl lo bf16 [128][GS]
    uint16_t* sl1 = sl0 + 128 * GS;                      // Wr lo
    {
        int tid = threadIdx.x;
        const float4* h0 = (const float4*)&g_whi[2 * layer][0];
        const float4* h1 = (const float4*)&g_whi[2 * layer + 1][0];
        const uint2*  l0 = (const uint2*) &g_wlo16[2 * layer][0];
        const uint2*  l1 = (const uint2*) &g_wlo16[2 * layer + 1][0];
        for (int i = tid; i < 4096; i += 512) {
            int k = i >> 5, c = i & 31;      // 128 elems/row, 4 per vec
            *(float4*)&swh0[k * GS + c * 4] = h0[i];
            *(float4*)&swh1[k * GS + c * 4] = h1[i];
            *(uint2*) &sl0 [k * GS + c * 4] = l0[i];
            *(uint2*) &sl1 [k * GS + c * 4] = l1[i];
        }
    }
    __syncthreads();

    int tid = threadIdx.x;
    int warp = tid >> 5, lane = tid & 31;
    int g = lane >> 2, tig = lane & 3;
    int wr = warp >> 1, half = warp & 1;
    int r0 = blockIdx.x * 128 + wr * 16;
    if (r0 >= NN) return;                    // tail rows % 16 == 0: clean

    const float*    __restrict__ swh = half ? swh1 : swh0;
    const uint16_t* __restrict__ swl = half ? sl1 : sl0;
    float* __restrict__ Cout = half ? g_xr : g_xl;

    const float* __restrict__ arow0 = A + (size_t)(r0 + g) * 128;
    const float* __restrict__ arow1 = A + (size_t)(r0 + g + 8) * 128;

    float acc[16][4];
    #pragma unroll
    for (int n = 0; n < 16; n++)
        #pragma unroll
        for (int j = 0; j < 4; j++) acc[n][j] = 0.f;

    #pragma unroll 4
    for (int ks = 0; ks < 16; ks++) {
        int k0 = ks * 8;
        uint32_t ah[4], al[4];
        tf32split(arow0[k0 + tig],     ah[0], al[0]);
        tf32split(arow1[k0 + tig],     ah[1], al[1]);
        tf32split(arow0[k0 + tig + 4], ah[2], al[2]);
        tf32split(arow1[k0 + tig + 4], ah[3], al[3]);

        const float*    sh0 = &swh[(k0 + tig) * GS + g];
        const float*    sh1 = &swh[(k0 + tig + 4) * GS + g];
        const uint16_t* sL0 = &swl[(k0 + tig) * GS + g];
        const uint16_t* sL1 = &swl[(k0 + tig + 4) * GS + g];

        #pragma unroll
        for (int n = 0; n < 16; n++) {
            uint32_t bh0 = __float_as_uint(sh0[n * 8]);
            uint32_t bh1 = __float_as_uint(sh1[n * 8]);
            uint32_t bl0 = ((uint32_t)sL0[n * 8]) << 16;   // bf16 -> tf32
            uint32_t bl1 = ((uint32_t)sL1[n * 8]) << 16;
            MMA_TF32(acc[n], ah[0], ah[1], ah[2], ah[3], bh0, bh1);
            MMA_TF32(acc[n], ah[0], ah[1], ah[2], ah[3], bl0, bl1);
            MMA_TF32(acc[n], al[0], al[1], al[2], al[3], bh0, bh1);
        }
    }

    float* c0 = Cout + (size_t)(r0 + g) * 128 + 2 * tig;
    float* c1 = Cout + (size_t)(r0 + g + 8) * 128 + 2 * tig;
    #pragma unroll
    for (int n = 0; n < 16; n++) {
        *(float2*)&c0[n * 8] = make_float2(acc[n][0], acc[n][1]);
        *(float2*)&c1[n * 8] = make_float2(acc[n][2], acc[n][3]);
    }
}

// ---------------- node-centric fused layers (warp per node) ------------------
#define EDGE_ZP(A, W, P)                                                        \
    {                                                                           \
        float z0 = (A).x + b.x + (W) * we.x; z0 = z0 > 0.f ? z0 : 0.2f * z0;   \
        float z1 = (A).y + b.y + (W) * we.y; z1 = z1 > 0.f ? z1 : 0.2f * z1;   \
        float z2 = (A).z + b.z + (W) * we.z; z2 = z2 > 0.f ? z2 : 0.2f * z2;   \
        float z3 = (A).w + b.w + (W) * we.w; z3 = z3 > 0.f ? z3 : 0.2f * z3;   \
        (P) = z0 * at.x + z1 * at.y + z2 * at.z + z3 * at.w;                    \
    }

__device__ __forceinline__ void node_core(int n, int lane,
        const float* __restrict__ We, const float* __restrict__ att,
        float4& acc, float& dsum) {
    float4 b  = *(const float4*)&g_xr[(size_t)n * 128 + lane * 4];
    float4 we = *(const float4*)&We[lane * 4];
    float4 at = *(const float4*)&att[lane * 4];

    // self loop first (hoisted out of the edge loop)
    {
        float4 a = *(const float4*)&g_xl[(size_t)n * 128 + lane * 4];
        float p;
        EDGE_ZP(a, g_ewsum * (1.0f / NE), p);
        p += __shfl_xor_sync(0xffffffffu, p, 1);
        p += __shfl_xor_sync(0xffffffffu, p, 2);
        p += __shfl_xor_sync(0xffffffffu, p, 4);
        float pe = __expf(p);
        acc = make_float4(pe * a.x, pe * a.y, pe * a.z, pe * a.w);
        dsum = pe;
    }

    int beg = g_ptr[n], end = g_ptr[n + 1];
    int i = beg;

    for (; i + 4 <= end; i += 4) {
        int   s0 = g_csr_src[i],     s1 = g_csr_src[i + 1];
        int   s2 = g_csr_src[i + 2], s3 = g_csr_src[i + 3];
        float w0 = g_csr_w[i],       w1 = g_csr_w[i + 1];
        float w2 = g_csr_w[i + 2],   w3 = g_csr_w[i + 3];

        float4 a0 = *(const float4*)&g_xl[(size_t)s0 * 128 + lane * 4];
        float4 a1 = *(const float4*)&g_xl[(size_t)s1 * 128 + lane * 4];
        float4 a2 = *(const float4*)&g_xl[(size_t)s2 * 128 + lane * 4];
        float4 a3 = *(const float4*)&g_xl[(size_t)s3 * 128 + lane * 4];

        float p0, p1, p2, p3;
        EDGE_ZP(a0, w0, p0); EDGE_ZP(a1, w1, p1);
        EDGE_ZP(a2, w2, p2); EDGE_ZP(a3, w3, p3);

        p0 += __shfl_xor_sync(0xffffffffu, p0, 1);
        p1 += __shfl_xor_sync(0xffffffffu, p1, 1);
        p2 += __shfl_xor_sync(0xffffffffu, p2, 1);
        p3 += __shfl_xor_sync(0xffffffffu, p3, 1);
        p0 += __shfl_xor_sync(0xffffffffu, p0, 2);
        p1 += __shfl_xor_sync(0xffffffffu, p1, 2);
        p2 += __shfl_xor_sync(0xffffffffu, p2, 2);
        p3 += __shfl_xor_sync(0xffffffffu, p3, 2);
        p0 += __shfl_xor_sync(0xffffffffu, p0, 4);
        p1 += __shfl_xor_sync(0xffffffffu, p1, 4);
        p2 += __shfl_xor_sync(0xffffffffu, p2, 4);
        p3 += __shfl_xor_sync(0xffffffffu, p3, 4);

        float e0 = __expf(p0), e1 = __expf(p1);
        float e2 = __expf(p2), e3 = __expf(p3);

        acc.x += e0 * a0.x + e1 * a1.x + e2 * a2.x + e3 * a3.x;
        acc.y += e0 * a0.y + e1 * a1.y + e2 * a2.y + e3 * a3.y;
        acc.z += e0 * a0.z + e1 * a1.z + e2 * a2.z + e3 * a3.z;
        acc.w += e0 * a0.w + e1 * a1.w + e2 * a2.w + e3 * a3.w;
        dsum += (e0 + e1) + (e2 + e3);
    }

    for (; i < end; i++) {
        int s = g_csr_src[i];
        float w = g_csr_w[i];
        float4 a = *(const float4*)&g_xl[(size_t)s * 128 + lane * 4];
        float p;
        EDGE_ZP(a, w, p);
        p += __shfl_xor_sync(0xffffffffu, p, 1);
        p += __shfl_xor_sync(0xffffffffu, p, 2);
        p += __shfl_xor_sync(0xffffffffu, p, 4);
        float pe = __expf(p);
        acc.x += pe * a.x; acc.y += pe * a.y;
        acc.z += pe * a.z; acc.w += pe * a.w;
        dsum += pe;
    }
}

// layer 1: writes g_h DIRECTLY (device-side symbol access; no host-passed ptr)
__global__ void k_node1(const float* __restrict__ We, const float* __restrict__ att,
                        const float* __restrict__ bias) {
    int n = (blockIdx.x * blockDim.x + threadIdx.x) >> 5;
    if (n >= NN) return;
    int lane = threadIdx.x & 31;
    float4 acc; float dsum;
    node_core(n, lane, We, att, acc, dsum);
    float inv = 1.0f / (dsum + 1e-16f);

    float4 bi = *(const float4*)&bias[lane * 4];
    float v0 = acc.x * inv + bi.x;
    float v1 = acc.y * inv + bi.y;
    float v2 = acc.z * inv + bi.z;
    float v3 = acc.w * inv + bi.w;
    v0 = v0 > 0.f ? v0 : (__expf(v0) - 1.f);
    v1 = v1 > 0.f ? v1 : (__expf(v1) - 1.f);
    v2 = v2 > 0.f ? v2 : (__expf(v2) - 1.f);
    v3 = v3 > 0.f ? v3 : (__expf(v3) - 1.f);
    *(float4*)&g_h[(size_t)n * 128 + lane * 4] = make_float4(v0, v1, v2, v3);
}

// layer 2: writes harness-provided d_out (valid device pointer argument)
__global__ void k_node2(const float* __restrict__ We, const float* __restrict__ att,
                        const float* __restrict__ bias, float* __restrict__ out) {
    int n = (blockIdx.x * blockDim.x + threadIdx.x) >> 5;
    if (n >= NN) return;
    int lane = threadIdx.x & 31;
    float4 acc; float dsum;
    node_core(n, lane, We, att, acc, dsum);
    float inv = 1.0f / (dsum + 1e-16f);

    float v0 = acc.x * inv, v1 = acc.y * inv, v2 = acc.z * inv, v3 = acc.w * inv;
    #pragma unroll
    for (int o = 8; o <= 16; o <<= 1) {
        v0 += __shfl_xor_sync(0xffffffffu, v0, o);
        v1 += __shfl_xor_sync(0xffffffffu, v1, o);
        v2 += __shfl_xor_sync(0xffffffffu, v2, o);
        v3 += __shfl_xor_sync(0xffffffffu, v3, o);
    }
    if (lane < 8) {
        float4 bi = *(const float4*)&bias[lane * 4];
        *(float4*)&out[(size_t)n * 32 + lane * 4] =
            make_float4(0.25f * v0 + bi.x, 0.25f * v1 + bi.y,
                        0.25f * v2 + bi.z, 0.25f * v3 + bi.w);
    }
}

// ---------------- launch ------------------------------------------------------
extern "C" void kernel_launch(void* const* d_in, const int* in_sizes, int n_in,
                              void* d_out, int out_size) {
    const float* x    = (const float*)d_in[0];
    const int*   ei   = (const int*)  d_in[1];
    const float* ew   = (const float*)d_in[2];
    const float* Wl1  = (const float*)d_in[3];
    const float* Wr1  = (const float*)d_in[4];
    const float* We1  = (const float*)d_in[5];
    const float* att1 = (const float*)d_in[6];
    const float* b1   = (const float*)d_in[7];
    const float* Wl2  = (const float*)d_in[8];
    const float* Wr2  = (const float*)d_in[9];
    const float* We2  = (const float*)d_in[10];
    const float* att2 = (const float*)d_in[11];
    const float* b2   = (const float*)d_in[12];
    float* out = (float*)d_out;

    const int* esrc = ei;
    const int* edst = ei + NE;

    cudaFuncSetAttribute(k_gemm2,
                         cudaFuncAttributeMaxDynamicSharedMemorySize, SMEM_G2);

    const int TC_BLK   = (NN + 127) / 128;              // 391
    const int NODE_BLK = (NN * 32 + 255) / 256;         // 6250 (warp per node)
    const int NE_BLK   = (NE + 255) / 256;              // 6250
    const int NN_BLK   = (NN + 255) / 256;              // 196

    // CSR build + prep (reused by both layers)
    k_hist_zero<<<NN_BLK, 256>>>();                     // also zeroes g_ewsum
    k_ew_reduce<<<448, 256>>>(ew);
    k_wsplit<<<256, 256>>>(Wl1, Wr1, Wl2, Wr2);
    k_hist<<<NE_BLK, 256>>>(edst);
    k_scan<<<1, 256>>>();
    k_scatter<<<NE_BLK, 256>>>(esrc, edst, ew);

    // ---- layer 1 ----
    k_gemm2<<<TC_BLK, 512, SMEM_G2>>>(x, 0, 0);         // [Wl1|Wr1] -> xl,xr
    k_node1<<<NODE_BLK, 256>>>(We1, att1, b1);

    // ---- layer 2 ----
    k_gemm2<<<TC_BLK, 512, SMEM_G2>>>(x, 1, 1);         // [Wl2|Wr2] -> xl,xr
    k_node2<<<NODE_BLK, 256>>>(We2, att2, b2, out);
}

// round 16
// speedup vs baseline: 1.7928x; 1.1558x over previous
#include <cuda_runtime.h>
#include <cuda_bf16.h>
#include <cstdint>

#define NN 50000
#define NE 1600000
#define FW 128         // H*C feature width
#define GS2 136        // smem stride in words: banks = 8*tig + g (+8n), conflict-free

// ---------------- scratch (device globals; no allocation allowed) ------------
__device__ float    g_xl[(size_t)NN * FW];
__device__ float    g_xr[(size_t)NN * FW];
__device__ float    g_h [(size_t)NN * FW];
__device__ float    g_ewsum;
__device__ uint32_t g_wbhi[4][64 * 128];   // bf16-hi pairs {k even,k odd} per word
__device__ uint32_t g_wblo[4][64 * 128];   // bf16-lo remainder pairs
__device__ int      g_deg[NN];             // histogram, then fill cursor
__device__ int      g_ptr[NN + 1];         // CSR row offsets (by dst)
__device__ int      g_csr_src[NE];
__device__ float    g_csr_w[NE];

// ---------------- edge-weight mean -------------------------------------------
__global__ void k_ew_reduce(const float* __restrict__ ew) {
    float s = 0.f;
    int stride = gridDim.x * blockDim.x;
    for (int i = blockIdx.x * blockDim.x + threadIdx.x; i < NE; i += stride)
        s += ew[i];
    #pragma unroll
    for (int o = 16; o; o >>= 1) s += __shfl_xor_sync(0xffffffffu, s, o);
    __shared__ float sm[8];
    int w = threadIdx.x >> 5, l = threadIdx.x & 31;
    if (l == 0) sm[w] = s;
    __syncthreads();
    if (threadIdx.x < 8) {
        s = sm[threadIdx.x];
        #pragma unroll
        for (int o = 4; o; o >>= 1) s += __shfl_xor_sync(0x000000ffu, s, o, 8);
        if (threadIdx.x == 0) atomicAdd(&g_ewsum, s);
    }
}

// ---------------- CSR build (once; reused by both layers) --------------------
__global__ void k_hist_zero() {
    int i = blockIdx.x * blockDim.x + threadIdx.x;
    if (i < NN) g_deg[i] = 0;
    if (i == 0) g_ewsum = 0.f;
}
__global__ void k_hist(const int* __restrict__ edst) {
    int i = blockIdx.x * blockDim.x + threadIdx.x;
    if (i < NE) atomicAdd(&g_deg[edst[i]], 1);
}
// single 256-thread block: exclusive scan g_deg -> g_ptr; g_deg := cursors
__global__ void k_scan() {
    const int CH = (NN + 255) / 256;       // 196
    int tid = threadIdx.x;                 // 0..255
    int lo = tid * CH;
    int hi = lo + CH; if (hi > NN) hi = NN;
    int s = 0;
    for (int i = lo; i < hi; i++) s += g_deg[i];

    __shared__ int wsum[8];
    int lane = tid & 31, w = tid >> 5;
    int v = s;
    #pragma unroll
    for (int o = 1; o < 32; o <<= 1) {
        int t = __shfl_up_sync(0xffffffffu, v, o);
        if (lane >= o) v += t;
    }
    if (lane == 31) wsum[w] = v;
    __syncthreads();
    if (tid == 0) {
        int run = 0;
        #pragma unroll
        for (int i = 0; i < 8; i++) { int t = wsum[i]; wsum[i] = run; run += t; }
    }
    __syncthreads();
    int run = (v - s) + wsum[w];           // exclusive prefix for this thread
    for (int i = lo; i < hi; i++) {
        int d = g_deg[i];
        g_ptr[i] = run;
        run += d;
    }
    if (tid == 0) g_ptr[NN] = NE;          // total degree == edge count
    __syncthreads();
    for (int i = lo; i < hi; i++) g_deg[i] = g_ptr[i];
}
__global__ void k_scatter(const int* __restrict__ esrc, const int* __restrict__ edst,
                          const float* __restrict__ ew) {
    int i = blockIdx.x * blockDim.x + threadIdx.x;
    if (i >= NE) return;
    int d = edst[i];
    int pos = atomicAdd(&g_deg[d], 1);
    g_csr_src[pos] = esrc[i];
    g_csr_w[pos]   = ew[i];
}

// ---------------- bf16 hi/lo split helpers -----------------------------------
__device__ __forceinline__ void bf16split1(float x, uint16_t& hi, uint16_t& lo) {
    __nv_bfloat16 h = __float2bfloat16(x);
    float r = x - __bfloat162float(h);
    __nv_bfloat16 l = __float2bfloat16(r);
    hi = __bfloat16_as_ushort(h);
    lo = __bfloat16_as_ushort(l);
}
__device__ __forceinline__ void bf16x2split(float2 v, uint32_t& hi, uint32_t& lo) {
    uint16_t h0, l0, h1, l1;
    bf16split1(v.x, h0, l0);
    bf16split1(v.y, h1, l1);
    hi = ((uint32_t)h1 << 16) | h0;        // element 0 (lower k) in low half
    lo = ((uint32_t)l1 << 16) | l0;
}

// split all four 128x128 W into packed bf16x2 hi/lo, keyed by k-pair
__global__ void k_wsplit(const float* __restrict__ W0, const float* __restrict__ W1,
                         const float* __restrict__ W2, const float* __restrict__ W3) {
    int i = blockIdx.x * blockDim.x + threadIdx.x;   // 0..32767
    if (i >= 4 * 8192) return;
    int m = i >> 13, j = i & 8191;                   // j = kp*128 + n
    int kp = j >> 7, n = j & 127;
    const float* W = (m == 0) ? W0 : (m == 1) ? W1 : (m == 2) ? W2 : W3;
    float2 v = make_float2(W[(2 * kp) * 128 + n], W[(2 * kp + 1) * 128 + n]);
    uint32_t hi, lo;
    bf16x2split(v, hi, lo);
    g_wbhi[m][j] = hi;
    g_wblo[m][j] = lo;
}

#define MMA_BF16(ACC, AH, B0, B1)                                               \
    asm volatile("mma.sync.aligned.m16n8k16.row.col.f32.bf16.bf16.f32 "         \
                 "{%0,%1,%2,%3},{%4,%5,%6,%7},{%8,%9},{%0,%1,%2,%3};"           \
                 : "+f"(ACC[0]), "+f"(ACC[1]), "+f"(ACC[2]), "+f"(ACC[3])       \
                 : "r"(AH[0]), "r"(AH[1]), "r"(AH[2]), "r"(AH[3]),              \
                   "r"(B0), "r"(B1))

// ---------------- merged dual GEMM: [xl|xr] = A @ [Wl|Wr] --------------------
// 3xBF16 (ah*bh + ah*bl + al*bh; split err 2^-18, dropped term 2^-18) on the
// FULL-RATE bf16 m16n8k16 HMMA path (2x the tf32 rate). One launch per layer;
// 512 thr = 16 warps = 8 row-groups x {Wl, Wr}; warp = 16 rows x 128 cols.
// B fragments from smem (hi+lo, GS2=136 conflict-free); A split on the fly.
#define SMEM_G2 (4 * 64 * GS2 * 4)                  // 139,264 B
__global__ void __launch_bounds__(512, 1) k_gemm2(
        const float* __restrict__ Aext, int asel, int layer) {
    const float* __restrict__ A = asel ? g_h : Aext;

    extern __shared__ uint32_t sb[];
    uint32_t* sbh0 = sb;                   // Wl hi [64][GS2]
    uint32_t* sbh1 = sb + 64 * GS2;        // Wr hi
    uint32_t* sbl0 = sb + 2 * 64 * GS2;    // Wl lo
    uint32_t* sbl1 = sb + 3 * 64 * GS2;    // Wr lo
    {
        int tid = threadIdx.x;
        const uint4* h0 = (const uint4*)&g_wbhi[2 * layer][0];
        const uint4* h1 = (const uint4*)&g_wbhi[2 * layer + 1][0];
        const uint4* l0 = (const uint4*)&g_wblo[2 * layer][0];
        const uint4* l1 = (const uint4*)&g_wblo[2 * layer + 1][0];
        for (int i = tid; i < 2048; i += 512) {      // 8192 words / 4
            int kp = i >> 5, c = i & 31;
            *(uint4*)&sbh0[kp * GS2 + c * 4] = h0[i];
            *(uint4*)&sbh1[kp * GS2 + c * 4] = h1[i];
            *(uint4*)&sbl0[kp * GS2 + c * 4] = l0[i];
            *(uint4*)&sbl1[kp * GS2 + c * 4] = l1[i];
        }
    }
    __syncthreads();

    int tid = threadIdx.x;
    int warp = tid >> 5, lane = tid & 31;
    int g = lane >> 2, tig = lane & 3;
    int wr = warp >> 1, half = warp & 1;
    int r0 = blockIdx.x * 128 + wr * 16;
    if (r0 >= NN) return;                  // tail rows % 16 == 0: clean

    const uint32_t* __restrict__ sbh = half ? sbh1 : sbh0;
    const uint32_t* __restrict__ sbl = half ? sbl1 : sbl0;
    float* __restrict__ Cout = half ? g_xr : g_xl;

    const float* __restrict__ arow0 = A + (size_t)(r0 + g) * 128;
    const float* __restrict__ arow1 = A + (size_t)(r0 + g + 8) * 128;

    float acc[16][4];
    #pragma unroll
    for (int n = 0; n < 16; n++)
        #pragma unroll
        for (int j = 0; j < 4; j++) acc[n][j] = 0.f;

    #pragma unroll 2
    for (int ks = 0; ks < 8; ks++) {
        int k0 = ks * 16, kp0 = ks * 8;

        // A fragment (m16n8k16): a0=row g k{2tig,+1}; a1=row g+8 same;
        //                        a2=row g k{2tig+8,+9}; a3=row g+8 same.
        float2 a00 = *(const float2*)&arow0[k0 + tig * 2];
        float2 a10 = *(const float2*)&arow1[k0 + tig * 2];
        float2 a01 = *(const float2*)&arow0[k0 + tig * 2 + 8];
        float2 a11 = *(const float2*)&arow1[k0 + tig * 2 + 8];

        uint32_t ah[4], al[4];
        bf16x2split(a00, ah[0], al[0]);
        bf16x2split(a10, ah[1], al[1]);
        bf16x2split(a01, ah[2], al[2]);
        bf16x2split(a11, ah[3], al[3]);

        // B fragment: b0 = kpair kp0+tig, b1 = kpair kp0+tig+4, col n*8+g
        const uint32_t* ph0 = &sbh[(kp0 + tig) * GS2 + g];
        const uint32_t* ph1 = &sbh[(kp0 + tig + 4) * GS2 + g];
        const uint32_t* pl0 = &sbl[(kp0 + tig) * GS2 + g];
        const uint32_t* pl1 = &sbl[(kp0 + tig + 4) * GS2 + g];

        #pragma unroll
        for (int n = 0; n < 16; n++) {
            uint32_t bh0 = ph0[n * 8], bh1 = ph1[n * 8];
            uint32_t bl0 = pl0[n * 8], bl1 = pl1[n * 8];
            MMA_BF16(acc[n], ah, bh0, bh1);
            MMA_BF16(acc[n], ah, bl0, bl1);
            MMA_BF16(acc[n], al, bh0, bh1);
        }
    }

    float* c0 = Cout + (size_t)(r0 + g) * 128 + 2 * tig;
    float* c1 = Cout + (size_t)(r0 + g + 8) * 128 + 2 * tig;
    #pragma unroll
    for (int n = 0; n < 16; n++) {
        *(float2*)&c0[n * 8] = make_float2(acc[n][0], acc[n][1]);
        *(float2*)&c1[n * 8] = make_float2(acc[n][2], acc[n][3]);
    }
}

// ---------------- node-centric fused layers (warp per node) ------------------
#define EDGE_ZP(A, W, P)                                                        \
    {                                                                           \
        float z0 = (A).x + b.x + (W) * we.x; z0 = z0 > 0.f ? z0 : 0.2f * z0;   \
        float z1 = (A).y + b.y + (W) * we.y; z1 = z1 > 0.f ? z1 : 0.2f * z1;   \
        float z2 = (A).z + b.z + (W) * we.z; z2 = z2 > 0.f ? z2 : 0.2f * z2;   \
        float z3 = (A).w + b.w + (W) * we.w; z3 = z3 > 0.f ? z3 : 0.2f * z3;   \
        (P) = z0 * at.x + z1 * at.y + z2 * at.z + z3 * at.w;                    \
    }

__device__ __forceinline__ void node_core(int n, int lane,
        const float* __restrict__ We, const float* __restrict__ att,
        float4& acc, float& dsum) {
    float4 b  = *(const float4*)&g_xr[(size_t)n * 128 + lane * 4];
    float4 we = *(const float4*)&We[lane * 4];
    float4 at = *(const float4*)&att[lane * 4];

    // self loop first (hoisted out of the edge loop)
    {
        float4 a = *(const float4*)&g_xl[(size_t)n * 128 + lane * 4];
        float p;
        EDGE_ZP(a, g_ewsum * (1.0f / NE), p);
        p += __shfl_xor_sync(0xffffffffu, p, 1);
        p += __shfl_xor_sync(0xffffffffu, p, 2);
        p += __shfl_xor_sync(0xffffffffu, p, 4);
        float pe = __expf(p);
        acc = make_float4(pe * a.x, pe * a.y, pe * a.z, pe * a.w);
        dsum = pe;
    }

    int beg = g_ptr[n], end = g_ptr[n + 1];
    int i = beg;

    for (; i + 4 <= end; i += 4) {
        int   s0 = g_csr_src[i],     s1 = g_csr_src[i + 1];
        int   s2 = g_csr_src[i + 2], s3 = g_csr_src[i + 3];
        float w0 = g_csr_w[i],       w1 = g_csr_w[i + 1];
        float w2 = g_csr_w[i + 2],   w3 = g_csr_w[i + 3];

        float4 a0 = *(const float4*)&g_xl[(size_t)s0 * 128 + lane * 4];
        float4 a1 = *(const float4*)&g_xl[(size_t)s1 * 128 + lane * 4];
        float4 a2 = *(const float4*)&g_xl[(size_t)s2 * 128 + lane * 4];
        float4 a3 = *(const float4*)&g_xl[(size_t)s3 * 128 + lane * 4];

        float p0, p1, p2, p3;
        EDGE_ZP(a0, w0, p0); EDGE_ZP(a1, w1, p1);
        EDGE_ZP(a2, w2, p2); EDGE_ZP(a3, w3, p3);

        p0 += __shfl_xor_sync(0xffffffffu, p0, 1);
        p1 += __shfl_xor_sync(0xffffffffu, p1, 1);
        p2 += __shfl_xor_sync(0xffffffffu, p2, 1);
        p3 += __shfl_xor_sync(0xffffffffu, p3, 1);
        p0 += __shfl_xor_sync(0xffffffffu, p0, 2);
        p1 += __shfl_xor_sync(0xffffffffu, p1, 2);
        p2 += __shfl_xor_sync(0xffffffffu, p2, 2);
        p3 += __shfl_xor_sync(0xffffffffu, p3, 2);
        p0 += __shfl_xor_sync(0xffffffffu, p0, 4);
        p1 += __shfl_xor_sync(0xffffffffu, p1, 4);
        p2 += __shfl_xor_sync(0xffffffffu, p2, 4);
        p3 += __shfl_xor_sync(0xffffffffu, p3, 4);

        float e0 = __expf(p0), e1 = __expf(p1);
        float e2 = __expf(p2), e3 = __expf(p3);

        acc.x += e0 * a0.x + e1 * a1.x + e2 * a2.x + e3 * a3.x;
        acc.y += e0 * a0.y + e1 * a1.y + e2 * a2.y + e3 * a3.y;
        acc.z += e0 * a0.z + e1 * a1.z + e2 * a2.z + e3 * a3.z;
        acc.w += e0 * a0.w + e1 * a1.w + e2 * a2.w + e3 * a3.w;
        dsum += (e0 + e1) + (e2 + e3);
    }

    for (; i < end; i++) {
        int s = g_csr_src[i];
        float w = g_csr_w[i];
        float4 a = *(const float4*)&g_xl[(size_t)s * 128 + lane * 4];
        float p;
        EDGE_ZP(a, w, p);
        p += __shfl_xor_sync(0xffffffffu, p, 1);
        p += __shfl_xor_sync(0xffffffffu, p, 2);
        p += __shfl_xor_sync(0xffffffffu, p, 4);
        float pe = __expf(p);
        acc.x += pe * a.x; acc.y += pe * a.y;
        acc.z += pe * a.z; acc.w += pe * a.w;
        dsum += pe;
    }
}

// layer 1: writes g_h DIRECTLY (device-side symbol access; no host-passed ptr)
__global__ void k_node1(const float* __restrict__ We, const float* __restrict__ att,
                        const float* __restrict__ bias) {
    int n = (blockIdx.x * blockDim.x + threadIdx.x) >> 5;
    if (n >= NN) return;
    int lane = threadIdx.x & 31;
    float4 acc; float dsum;
    node_core(n, lane, We, att, acc, dsum);
    float inv = 1.0f / (dsum + 1e-16f);

    float4 bi = *(const float4*)&bias[lane * 4];
    float v0 = acc.x * inv + bi.x;
    float v1 = acc.y * inv + bi.y;
    float v2 = acc.z * inv + bi.z;
    float v3 = acc.w * inv + bi.w;
    v0 = v0 > 0.f ? v0 : (__expf(v0) - 1.f);
    v1 = v1 > 0.f ? v1 : (__expf(v1) - 1.f);
    v2 = v2 > 0.f ? v2 : (__expf(v2) - 1.f);
    v3 = v3 > 0.f ? v3 : (__expf(v3) - 1.f);
    *(float4*)&g_h[(size_t)n * 128 + lane * 4] = make_float4(v0, v1, v2, v3);
}

// layer 2: writes harness-provided d_out (valid device pointer argument)
__global__ void k_node2(const float* __restrict__ We, const float* __restrict__ att,
                        const float* __restrict__ bias, float* __restrict__ out) {
    int n = (blockIdx.x * blockDim.x + threadIdx.x) >> 5;
    if (n >= NN) return;
    int lane = threadIdx.x & 31;
    float4 acc; float dsum;
    node_core(n, lane, We, att, acc, dsum);
    float inv = 1.0f / (dsum + 1e-16f);

    float v0 = acc.x * inv, v1 = acc.y * inv, v2 = acc.z * inv, v3 = acc.w * inv;
    #pragma unroll
    for (int o = 8; o <= 16; o <<= 1) {
        v0 += __shfl_xor_sync(0xffffffffu, v0, o);
        v1 += __shfl_xor_sync(0xffffffffu, v1, o);
        v2 += __shfl_xor_sync(0xffffffffu, v2, o);
        v3 += __shfl_xor_sync(0xffffffffu, v3, o);
    }
    if (lane < 8) {
        float4 bi = *(const float4*)&bias[lane * 4];
        *(float4*)&out[(size_t)n * 32 + lane * 4] =
            make_float4(0.25f * v0 + bi.x, 0.25f * v1 + bi.y,
                        0.25f * v2 + bi.z, 0.25f * v3 + bi.w);
    }
}

// ---------------- launch ------------------------------------------------------
extern "C" void kernel_launch(void* const* d_in, const int* in_sizes, int n_in,
                              void* d_out, int out_size) {
    const float* x    = (const float*)d_in[0];
    const int*   ei   = (const int*)  d_in[1];
    const float* ew   = (const float*)d_in[2];
    const float* Wl1  = (const float*)d_in[3];
    const float* Wr1  = (const float*)d_in[4];
    const float* We1  = (const float*)d_in[5];
    const float* att1 = (const float*)d_in[6];
    const float* b1   = (const float*)d_in[7];
    const float* Wl2  = (const float*)d_in[8];
    const float* Wr2  = (const float*)d_in[9];
    const float* We2  = (const float*)d_in[10];
    const float* att2 = (const float*)d_in[11];
    const float* b2   = (const float*)d_in[12];
    float* out = (float*)d_out;

    const int* esrc = ei;
    const int* edst = ei + NE;

    cudaFuncSetAttribute(k_gemm2,
                         cudaFuncAttributeMaxDynamicSharedMemorySize, SMEM_G2);

    const int TC_BLK   = (NN + 127) / 128;              // 391
    const int NODE_BLK = (NN * 32 + 255) / 256;         // 6250 (warp per node)
    const int NE_BLK   = (NE + 255) / 256;              // 6250
    const int NN_BLK   = (NN + 255) / 256;              // 196

    // CSR build + prep (reused by both layers)
    k_hist_zero<<<NN_BLK, 256>>>();                     // also zeroes g_ewsum
    k_ew_reduce<<<448, 256>>>(ew);
    k_wsplit<<<128, 256>>>(Wl1, Wr1, Wl2, Wr2);
    k_hist<<<NE_BLK, 256>>>(edst);
    k_scan<<<1, 256>>>();
    k_scatter<<<NE_BLK, 256>>>(esrc, edst, ew);

    // ---- layer 1 ----
    k_gemm2<<<TC_BLK, 512, SMEM_G2>>>(x, 0, 0);         // [Wl1|Wr1] -> xl,xr
    k_node1<<<NODE_BLK, 256>>>(We1, att1, b1);

    // ---- layer 2 ----
    k_gemm2<<<TC_BLK, 512, SMEM_G2>>>(x, 1, 1);         // [Wl2|Wr2] -> xl,xr
    k_node2<<<NODE_BLK, 256>>>(We2, att2, b2, out);
}

// round 17
// speedup vs baseline: 1.8229x; 1.0168x over previous
#include <cuda_runtime.h>
#include <cuda_bf16.h>
#include <cstdint>

#define NN 50000
#define NE 1600000
#define FW 128         // H*C feature width
#define GS2 136        // smem stride in words: banks = 8*tig + g (+8n), conflict-free

// ---------------- scratch (device globals; no allocation allowed) ------------
__device__ float    g_xl[(size_t)NN * FW];
__device__ float    g_xr[(size_t)NN * FW];
__device__ float    g_h [(size_t)NN * FW];
__device__ float    g_ewsum;
__device__ uint32_t g_wbhi[4][64 * 128];   // bf16-hi pairs {k even,k odd} per word
__device__ uint32_t g_wblo[4][64 * 128];   // bf16-lo remainder pairs
__device__ int      g_deg[NN];             // histogram, then fill cursor
__device__ int      g_ptr[NN + 1];         // CSR row offsets (by dst)
__device__ int2     g_csr[NE];             // interleaved {src, w-bits}

// ---------------- CSR build (once; reused by both layers) --------------------
__global__ void k_hist_zero() {
    int i = blockIdx.x * blockDim.x + threadIdx.x;
    if (i < NN) g_deg[i] = 0;
    if (i == 0) g_ewsum = 0.f;
}
// fused: histogram by dst + edge-weight sum (one pass over the edge stream)
__global__ void k_hist(const int* __restrict__ edst, const float* __restrict__ ew) {
    float s = 0.f;
    int stride = gridDim.x * blockDim.x;
    for (int i = blockIdx.x * blockDim.x + threadIdx.x; i < NE; i += stride) {
        atomicAdd(&g_deg[edst[i]], 1);
        s += ew[i];
    }
    #pragma unroll
    for (int o = 16; o; o >>= 1) s += __shfl_xor_sync(0xffffffffu, s, o);
    __shared__ float sm[8];
    int w = threadIdx.x >> 5, l = threadIdx.x & 31;
    if (l == 0) sm[w] = s;
    __syncthreads();
    if (threadIdx.x < 8) {
        s = sm[threadIdx.x];
        #pragma unroll
        for (int o = 4; o; o >>= 1) s += __shfl_xor_sync(0x000000ffu, s, o, 8);
        if (threadIdx.x == 0) atomicAdd(&g_ewsum, s);
    }
}
// single 256-thread block: exclusive scan g_deg -> g_ptr; g_deg := cursors
__global__ void k_scan() {
    const int CH = (NN + 255) / 256;       // 196
    int tid = threadIdx.x;                 // 0..255
    int lo = tid * CH;
    int hi = lo + CH; if (hi > NN) hi = NN;
    int s = 0;
    for (int i = lo; i < hi; i++) s += g_deg[i];

    __shared__ int wsum[8];
    int lane = tid & 31, w = tid >> 5;
    int v = s;
    #pragma unroll
    for (int o = 1; o < 32; o <<= 1) {
        int t = __shfl_up_sync(0xffffffffu, v, o);
        if (lane >= o) v += t;
    }
    if (lane == 31) wsum[w] = v;
    __syncthreads();
    if (tid == 0) {
        int run = 0;
        #pragma unroll
        for (int i = 0; i < 8; i++) { int t = wsum[i]; wsum[i] = run; run += t; }
    }
    __syncthreads();
    int run = (v - s) + wsum[w];           // exclusive prefix for this thread
    for (int i = lo; i < hi; i++) {
        int d = g_deg[i];
        g_ptr[i] = run;
        run += d;
    }
    if (tid == 0) g_ptr[NN] = NE;          // total degree == edge count
    __syncthreads();
    for (int i = lo; i < hi; i++) g_deg[i] = g_ptr[i];
}
__global__ void k_scatter(const int* __restrict__ esrc, const int* __restrict__ edst,
                          const float* __restrict__ ew) {
    int i = blockIdx.x * blockDim.x + threadIdx.x;
    if (i >= NE) return;
    int d = edst[i];
    int pos = atomicAdd(&g_deg[d], 1);
    g_csr[pos] = make_int2(esrc[i], __float_as_int(ew[i]));
}

// ---------------- bf16 hi/lo split helpers -----------------------------------
__device__ __forceinline__ void bf16split1(float x, uint16_t& hi, uint16_t& lo) {
    __nv_bfloat16 h = __float2bfloat16(x);
    float r = x - __bfloat162float(h);
    __nv_bfloat16 l = __float2bfloat16(r);
    hi = __bfloat16_as_ushort(h);
    lo = __bfloat16_as_ushort(l);
}
__device__ __forceinline__ void bf16x2split(float2 v, uint32_t& hi, uint32_t& lo) {
    uint16_t h0, l0, h1, l1;
    bf16split1(v.x, h0, l0);
    bf16split1(v.y, h1, l1);
    hi = ((uint32_t)h1 << 16) | h0;        // element 0 (lower k) in low half
    lo = ((uint32_t)l1 << 16) | l0;
}

// split all four 128x128 W into packed bf16x2 hi/lo, keyed by k-pair
__global__ void k_wsplit(const float* __restrict__ W0, const float* __restrict__ W1,
                         const float* __restrict__ W2, const float* __restrict__ W3) {
    int i = blockIdx.x * blockDim.x + threadIdx.x;   // 0..32767
    if (i >= 4 * 8192) return;
    int m = i >> 13, j = i & 8191;                   // j = kp*128 + n
    int kp = j >> 7, n = j & 127;
    const float* W = (m == 0) ? W0 : (m == 1) ? W1 : (m == 2) ? W2 : W3;
    float2 v = make_float2(W[(2 * kp) * 128 + n], W[(2 * kp + 1) * 128 + n]);
    uint32_t hi, lo;
    bf16x2split(v, hi, lo);
    g_wbhi[m][j] = hi;
    g_wblo[m][j] = lo;
}

#define MMA_BF16(ACC, AH, B0, B1)                                               \
    asm volatile("mma.sync.aligned.m16n8k16.row.col.f32.bf16.bf16.f32 "         \
                 "{%0,%1,%2,%3},{%4,%5,%6,%7},{%8,%9},{%0,%1,%2,%3};"           \
                 : "+f"(ACC[0]), "+f"(ACC[1]), "+f"(ACC[2]), "+f"(ACC[3])       \
                 : "r"(AH[0]), "r"(AH[1]), "r"(AH[2]), "r"(AH[3]),              \
                   "r"(B0), "r"(B1))

// ---------------- merged dual GEMM: [xl|xr] = A @ [Wl|Wr] --------------------
// 3xBF16 (ah*bh + ah*bl + al*bh) on the full-rate bf16 m16n8k16 HMMA path.
#define SMEM_G2 (4 * 64 * GS2 * 4)                  // 139,264 B
__global__ void __launch_bounds__(512, 1) k_gemm2(
        const float* __restrict__ Aext, int asel, int layer) {
    const float* __restrict__ A = asel ? g_h : Aext;

    extern __shared__ uint32_t sb[];
    uint32_t* sbh0 = sb;                   // Wl hi [64][GS2]
    uint32_t* sbh1 = sb + 64 * GS2;        // Wr hi
    uint32_t* sbl0 = sb + 2 * 64 * GS2;    // Wl lo
    uint32_t* sbl1 = sb + 3 * 64 * GS2;    // Wr lo
    {
        int tid = threadIdx.x;
        const uint4* h0 = (const uint4*)&g_wbhi[2 * layer][0];
        const uint4* h1 = (const uint4*)&g_wbhi[2 * layer + 1][0];
        const uint4* l0 = (const uint4*)&g_wblo[2 * layer][0];
        const uint4* l1 = (const uint4*)&g_wblo[2 * layer + 1][0];
        for (int i = tid; i < 2048; i += 512) {      // 8192 words / 4
            int kp = i >> 5, c = i & 31;
            *(uint4*)&sbh0[kp * GS2 + c * 4] = h0[i];
            *(uint4*)&sbh1[kp * GS2 + c * 4] = h1[i];
            *(uint4*)&sbl0[kp * GS2 + c * 4] = l0[i];
            *(uint4*)&sbl1[kp * GS2 + c * 4] = l1[i];
        }
    }
    __syncthreads();

    int tid = threadIdx.x;
    int warp = tid >> 5, lane = tid & 31;
    int g = lane >> 2, tig = lane & 3;
    int wr = warp >> 1, half = warp & 1;
    int r0 = blockIdx.x * 128 + wr * 16;
    if (r0 >= NN) return;                  // tail rows % 16 == 0: clean

    const uint32_t* __restrict__ sbh = half ? sbh1 : sbh0;
    const uint32_t* __restrict__ sbl = half ? sbl1 : sbl0;
    float* __restrict__ Cout = half ? g_xr : g_xl;

    const float* __restrict__ arow0 = A + (size_t)(r0 + g) * 128;
    const float* __restrict__ arow1 = A + (size_t)(r0 + g + 8) * 128;

    float acc[16][4];
    #pragma unroll
    for (int n = 0; n < 16; n++)
        #pragma unroll
        for (int j = 0; j < 4; j++) acc[n][j] = 0.f;

    #pragma unroll 2
    for (int ks = 0; ks < 8; ks++) {
        int k0 = ks * 16, kp0 = ks * 8;

        float2 a00 = *(const float2*)&arow0[k0 + tig * 2];
        float2 a10 = *(const float2*)&arow1[k0 + tig * 2];
        float2 a01 = *(const float2*)&arow0[k0 + tig * 2 + 8];
        float2 a11 = *(const float2*)&arow1[k0 + tig * 2 + 8];

        uint32_t ah[4], al[4];
        bf16x2split(a00, ah[0], al[0]);
        bf16x2split(a10, ah[1], al[1]);
        bf16x2split(a01, ah[2], al[2]);
        bf16x2split(a11, ah[3], al[3]);

        const uint32_t* ph0 = &sbh[(kp0 + tig) * GS2 + g];
        const uint32_t* ph1 = &sbh[(kp0 + tig + 4) * GS2 + g];
        const uint32_t* pl0 = &sbl[(kp0 + tig) * GS2 + g];
        const uint32_t* pl1 = &sbl[(kp0 + tig + 4) * GS2 + g];

        #pragma unroll
        for (int n = 0; n < 16; n++) {
            uint32_t bh0 = ph0[n * 8], bh1 = ph1[n * 8];
            uint32_t bl0 = pl0[n * 8], bl1 = pl1[n * 8];
            MMA_BF16(acc[n], ah, bh0, bh1);
            MMA_BF16(acc[n], ah, bl0, bl1);
            MMA_BF16(acc[n], al, bh0, bh1);
        }
    }

    float* c0 = Cout + (size_t)(r0 + g) * 128 + 2 * tig;
    float* c1 = Cout + (size_t)(r0 + g + 8) * 128 + 2 * tig;
    #pragma unroll
    for (int n = 0; n < 16; n++) {
        *(float2*)&c0[n * 8] = make_float2(acc[n][0], acc[n][1]);
        *(float2*)&c1[n * 8] = make_float2(acc[n][2], acc[n][3]);
    }
}

// ---------------- node-centric fused layers (warp per node) ------------------
#define EDGE_ZP(A, W, P)                                                        \
    {                                                                           \
        float z0 = (A).x + b.x + (W) * we.x; z0 = z0 > 0.f ? z0 : 0.2f * z0;   \
        float z1 = (A).y + b.y + (W) * we.y; z1 = z1 > 0.f ? z1 : 0.2f * z1;   \
        float z2 = (A).z + b.z + (W) * we.z; z2 = z2 > 0.f ? z2 : 0.2f * z2;   \
        float z3 = (A).w + b.w + (W) * we.w; z3 = z3 > 0.f ? z3 : 0.2f * z3;   \
        (P) = z0 * at.x + z1 * at.y + z2 * at.z + z3 * at.w;                    \
    }

#define SHFL3(P)                                                                \
    (P) += __shfl_xor_sync(0xffffffffu, (P), 1);                                \
    (P) += __shfl_xor_sync(0xffffffffu, (P), 2);                                \
    (P) += __shfl_xor_sync(0xffffffffu, (P), 4);

__device__ __forceinline__ void node_core(int n, int lane,
        const float* __restrict__ We, const float* __restrict__ att,
        float4& acc, float& dsum) {
    float4 b  = *(const float4*)&g_xr[(size_t)n * 128 + lane * 4];
    float4 we = *(const float4*)&We[lane * 4];
    float4 at = *(const float4*)&att[lane * 4];

    // self loop first (hoisted out of the edge loop)
    {
        float4 a = *(const float4*)&g_xl[(size_t)n * 128 + lane * 4];
        float p;
        EDGE_ZP(a, g_ewsum * (1.0f / NE), p);
        SHFL3(p);
        float pe = __expf(p);
        acc = make_float4(pe * a.x, pe * a.y, pe * a.z, pe * a.w);
        dsum = pe;
    }

    int beg = g_ptr[n], end = g_ptr[n + 1];
    int i = beg;

    // unroll-8: 8 independent gathers (MLP=8) + 8 interleavable chains
    for (; i + 8 <= end; i += 8) {
        int2 e0 = g_csr[i],     e1 = g_csr[i + 1];
        int2 e2 = g_csr[i + 2], e3 = g_csr[i + 3];
        int2 e4 = g_csr[i + 4], e5 = g_csr[i + 5];
        int2 e6 = g_csr[i + 6], e7 = g_csr[i + 7];

        float4 a0 = *(const float4*)&g_xl[(size_t)e0.x * 128 + lane * 4];
        float4 a1 = *(const float4*)&g_xl[(size_t)e1.x * 128 + lane * 4];
        float4 a2 = *(const float4*)&g_xl[(size_t)e2.x * 128 + lane * 4];
        float4 a3 = *(const float4*)&g_xl[(size_t)e3.x * 128 + lane * 4];
        float4 a4 = *(const float4*)&g_xl[(size_t)e4.x * 128 + lane * 4];
        float4 a5 = *(const float4*)&g_xl[(size_t)e5.x * 128 + lane * 4];
        float4 a6 = *(const float4*)&g_xl[(size_t)e6.x * 128 + lane * 4];
        float4 a7 = *(const float4*)&g_xl[(size_t)e7.x * 128 + lane * 4];

        float p0, p1, p2, p3, p4, p5, p6, p7;
        EDGE_ZP(a0, __int_as_float(e0.y), p0);
        EDGE_ZP(a1, __int_as_float(e1.y), p1);
        EDGE_ZP(a2, __int_as_float(e2.y), p2);
        EDGE_ZP(a3, __int_as_float(e3.y), p3);
        EDGE_ZP(a4, __int_as_float(e4.y), p4);
        EDGE_ZP(a5, __int_as_float(e5.y), p5);
        EDGE_ZP(a6, __int_as_float(e6.y), p6);
        EDGE_ZP(a7, __int_as_float(e7.y), p7);

        p0 += __shfl_xor_sync(0xffffffffu, p0, 1);
        p1 += __shfl_xor_sync(0xffffffffu, p1, 1);
        p2 += __shfl_xor_sync(0xffffffffu, p2, 1);
        p3 += __shfl_xor_sync(0xffffffffu, p3, 1);
        p4 += __shfl_xor_sync(0xffffffffu, p4, 1);
        p5 += __shfl_xor_sync(0xffffffffu, p5, 1);
        p6 += __shfl_xor_sync(0xffffffffu, p6, 1);
        p7 += __shfl_xor_sync(0xffffffffu, p7, 1);
        p0 += __shfl_xor_sync(0xffffffffu, p0, 2);
        p1 += __shfl_xor_sync(0xffffffffu, p1, 2);
        p2 += __shfl_xor_sync(0xffffffffu, p2, 2);
        p3 += __shfl_xor_sync(0xffffffffu, p3, 2);
        p4 += __shfl_xor_sync(0xffffffffu, p4, 2);
        p5 += __shfl_xor_sync(0xffffffffu, p5, 2);
        p6 += __shfl_xor_sync(0xffffffffu, p6, 2);
        p7 += __shfl_xor_sync(0xffffffffu, p7, 2);
        p0 += __shfl_xor_sync(0xffffffffu, p0, 4);
        p1 += __shfl_xor_sync(0xffffffffu, p1, 4);
        p2 += __shfl_xor_sync(0xffffffffu, p2, 4);
        p3 += __shfl_xor_sync(0xffffffffu, p3, 4);
        p4 += __shfl_xor_sync(0xffffffffu, p4, 4);
        p5 += __shfl_xor_sync(0xffffffffu, p5, 4);
        p6 += __shfl_xor_sync(0xffffffffu, p6, 4);
        p7 += __shfl_xor_sync(0xffffffffu, p7, 4);

        float q0 = __expf(p0), q1 = __expf(p1), q2 = __expf(p2), q3 = __expf(p3);
        float q4 = __expf(p4), q5 = __expf(p5), q6 = __expf(p6), q7 = __expf(p7);

        acc.x += q0 * a0.x + q1 * a1.x + q2 * a2.x + q3 * a3.x
               + q4 * a4.x + q5 * a5.x + q6 * a6.x + q7 * a7.x;
        acc.y += q0 * a0.y + q1 * a1.y + q2 * a2.y + q3 * a3.y
               + q4 * a4.y + q5 * a5.y + q6 * a6.y + q7 * a7.y;
        acc.z += q0 * a0.z + q1 * a1.z + q2 * a2.z + q3 * a3.z
               + q4 * a4.z + q5 * a5.z + q6 * a6.z + q7 * a7.z;
        acc.w += q0 * a0.w + q1 * a1.w + q2 * a2.w + q3 * a3.w
               + q4 * a4.w + q5 * a5.w + q6 * a6.w + q7 * a7.w;
        dsum += ((q0 + q1) + (q2 + q3)) + ((q4 + q5) + (q6 + q7));
    }

    for (; i < end; i++) {
        int2 e = g_csr[i];
        float4 a = *(const float4*)&g_xl[(size_t)e.x * 128 + lane * 4];
        float p;
        EDGE_ZP(a, __int_as_float(e.y), p);
        SHFL3(p);
        float pe = __expf(p);
        acc.x += pe * a.x; acc.y += pe * a.y;
        acc.z += pe * a.z; acc.w += pe * a.w;
        dsum += pe;
    }
}

// layer 1: writes g_h DIRECTLY (device-side symbol access; no host-passed ptr)
__global__ void k_node1(const float* __restrict__ We, const float* __restrict__ att,
                        const float* __restrict__ bias) {
    int n = (blockIdx.x * blockDim.x + threadIdx.x) >> 5;
    if (n >= NN) return;
    int lane = threadIdx.x & 31;
    float4 acc; float dsum;
    node_core(n, lane, We, att, acc, dsum);
    float inv = 1.0f / (dsum + 1e-16f);

    float4 bi = *(const float4*)&bias[lane * 4];
    float v0 = acc.x * inv + bi.x;
    float v1 = acc.y * inv + bi.y;
    float v2 = acc.z * inv + bi.z;
    float v3 = acc.w * inv + bi.w;
    v0 = v0 > 0.f ? v0 : (__expf(v0) - 1.f);
    v1 = v1 > 0.f ? v1 : (__expf(v1) - 1.f);
    v2 = v2 > 0.f ? v2 : (__expf(v2) - 1.f);
    v3 = v3 > 0.f ? v3 : (__expf(v3) - 1.f);
    *(float4*)&g_h[(size_t)n * 128 + lane * 4] = make_float4(v0, v1, v2, v3);
}

// layer 2: writes harness-provided d_out (valid device pointer argument)
__global__ void k_node2(const float* __restrict__ We, const float* __restrict__ att,
                        const float* __restrict__ bias, float* __restrict__ out) {
    int n = (blockIdx.x * blockDim.x + threadIdx.x) >> 5;
    if (n >= NN) return;
    int lane = threadIdx.x & 31;
    float4 acc; float dsum;
    node_core(n, lane, We, att, acc, dsum);
    float inv = 1.0f / (dsum + 1e-16f);

    float v0 = acc.x * inv, v1 = acc.y * inv, v2 = acc.z * inv, v3 = acc.w * inv;
    // mean over heads: lanes {c, c+8, c+16, c+24} hold the same channels
    #pragma unroll
    for (int o = 8; o <= 16; o <<= 1) {
        v0 += __shfl_xor_sync(0xffffffffu, v0, o);
        v1 += __shfl_xor_sync(0xffffffffu, v1, o);
        v2 += __shfl_xor_sync(0xffffffffu, v2, o);
        v3 += __shfl_xor_sync(0xffffffffu, v3, o);
    }
    if (lane < 8) {
        float4 bi = *(const float4*)&bias[lane * 4];
        *(float4*)&out[(size_t)n * 32 + lane * 4] =
            make_float4(0.25f * v0 + bi.x, 0.25f * v1 + bi.y,
                        0.25f * v2 + bi.z, 0.25f * v3 + bi.w);
    }
}

// ---------------- launch ------------------------------------------------------
extern "C" void kernel_launch(void* const* d_in, const int* in_sizes, int n_in,
                              void* d_out, int out_size) {
    const float* x    = (const float*)d_in[0];
    const int*   ei   = (const int*)  d_in[1];
    const float* ew   = (const float*)d_in[2];
    const float* Wl1  = (const float*)d_in[3];
    const float* Wr1  = (const float*)d_in[4];
    const float* We1  = (const float*)d_in[5];
    const float* att1 = (const float*)d_in[6];
    const float* b1   = (const float*)d_in[7];
    const float* Wl2  = (const float*)d_in[8];
    const float* Wr2  = (const float*)d_in[9];
    const float* We2  = (const float*)d_in[10];
    const float* att2 = (const float*)d_in[11];
    const float* b2   = (const float*)d_in[12];
    float* out = (float*)d_out;

    const int* esrc = ei;
    const int* edst = ei + NE;

    cudaFuncSetAttribute(k_gemm2,
                         cudaFuncAttributeMaxDynamicSharedMemorySize, SMEM_G2);

    const int TC_BLK   = (NN + 127) / 128;              // 391
    const int NODE_BLK = (NN * 32 + 255) / 256;         // 6250 (warp per node)
    const int NE_BLK   = (NE + 255) / 256;              // 6250
    const int NN_BLK   = (NN + 255) / 256;              // 196

    // CSR build + prep (reused by both layers)
    k_hist_zero<<<NN_BLK, 256>>>();                     // zeroes deg + ewsum
    k_wsplit<<<128, 256>>>(Wl1, Wr1, Wl2, Wr2);
    k_hist<<<448, 256>>>(edst, ew);                     // hist + ewsum fused
    k_scan<<<1, 256>>>();
    k_scatter<<<NE_BLK, 256>>>(esrc, edst, ew);

    // ---- layer 1 ----
    k_gemm2<<<TC_BLK, 512, SMEM_G2>>>(x, 0, 0);         // [Wl1|Wr1] -> xl,xr
    k_node1<<<NODE_BLK, 256>>>(We1, att1, b1);

    // ---- layer 2 ----
    k_gemm2<<<TC_BLK, 512, SMEM_G2>>>(x, 1, 1);         // [Wl2|Wr2] -> xl,xr
    k_node2<<<NODE_BLK, 256>>>(We2, att2, b2, out);
}